// round 2
// baseline (speedup 1.0000x reference)
#include <cuda_runtime.h>
#include <math.h>

// ---------------------------------------------------------------------------
// LaCT SWIGLU fast-weight self-attention, fp32 SIMT baseline.
// BH=8, T=4096, D=DI=512, CS=256. 15 update chunks + 1 forward-only chunk.
// All GEMMs go through one generic strided NT-form kernel:
//   C[r,c] = alpha * sum_k A(r,k)*B(c,k)  (+ beta * Dm[r,c])
// Symmetry of X@X^T and A@A is exact (identical FMA order), so every
// Newton-Schulz GEMM is NT-form too.
// ---------------------------------------------------------------------------

#define BH 8
#define TT 4096
#define DD 512
#define DI 512
#define CS 256
#define NCHUNK 15          // T/CS - 1
#define NMAT 24            // 3 weights * BH
#define MSZ (512 * 512)    // elements per weight matrix
#define EW1_N (BH * DI * CS)
#define EW2_N (BH * CS * DD)

// ------------------------- device scratch ----------------------------------
__device__ float g_wm[NMAT][MSZ];     // momentum-accumulated (unnormalized) weights
__device__ float g_wc[NMAT][MSZ];     // current (normalized) weights used in fwd/bwd
__device__ float g_dm[NMAT][MSZ];     // momentum buffer (= previous dw)
__device__ float g_dw[NMAT][MSZ];     // raw grads from this chunk
__device__ float g_wnorm[NMAT][512];  // original per-row norms
__device__ float g_X0[NMAT][MSZ];     // NS ping
__device__ float g_X1[NMAT][MSZ];     // NS pong
__device__ float g_Ab[NMAT][MSZ];     // NS A = X X^T
__device__ float g_Bb[NMAT][MSZ];     // NS B = b*A + c*A*A

__device__ float g_gba[EW1_N];        // w0c @ k^T
__device__ float g_hbm[EW1_N];        // w2c @ k^T
__device__ float g_hh[EW1_N];         // w2c @ q^T
__device__ float g_g0[EW1_N];         // w0c @ q^T
__device__ float g_dhid[EW1_N];       // w1c^T @ v^T
__device__ float g_gh[EW1_N];         // silu(g0)*h
__device__ float g_hl1[EW1_N];        // hidden * l1
__device__ float g_dhbm[EW1_N];
__device__ float g_dgba[EW1_N];
__device__ float g_kl0[EW2_N];        // k * lr0
__device__ float g_kl2[EW2_N];        // k * lr2
__device__ float g_mi[BH];
__device__ float g_mli[BH];
__device__ float g_rns[NMAT];         // 1/(frob(dm)+1e-7)

// ------------------------- generic GEMM ------------------------------------
struct GArgs {
    const float* A; int asr, ask; long abs_;
    const float* B; int bsr, bsk; long bbs;
    float*       C; int csr, csc; long cbs;
    const float* Dm; long dbs;         // Dm shares C's (csr,csc)
    int K;
    float alpha, beta;
};

// 128x128 tile, TK=8, 256 threads, 8x8 per thread (two 4x4 quads).
__global__ __launch_bounds__(256, 2) void gemm_k(GArgs g) {
    __shared__ __align__(16) float As[8][132];  // pad 132 -> conflict-free STS
    __shared__ __align__(16) float Bs[8][132];

    const int b = blockIdx.z;
    const float* A = g.A + (long)b * g.abs_;
    const float* B = g.B + (long)b * g.bbs;
    const int row0 = blockIdx.y * 128;
    const int col0 = blockIdx.x * 128;
    const int tid = threadIdx.x;
    const int tx = tid & 15, ty = tid >> 4;

    float acc[8][8];
#pragma unroll
    for (int i = 0; i < 8; i++)
#pragma unroll
        for (int j = 0; j < 8; j++) acc[i][j] = 0.f;

    const bool aKfast = (g.ask == 1);
    const bool bKfast = (g.bsk == 1);

    for (int kt = 0; kt < g.K; kt += 8) {
        if (aKfast) {
            int kk = tid & 7, r = tid >> 3;  // 32 rows/pass
            const float* p = A + (long)(row0 + r) * g.asr + (kt + kk);
#pragma unroll
            for (int ps = 0; ps < 4; ps++)
                As[kk][r + ps * 32] = p[(long)ps * 32 * g.asr];
        } else {  // row-contiguous operand (asr expected 1)
            int r = tid & 127, kk = tid >> 7;  // 2 k/pass
            const float* p = A + (long)(kt + kk) * g.ask + (long)(row0 + r) * g.asr;
#pragma unroll
            for (int ps = 0; ps < 4; ps++)
                As[kk + ps * 2][r] = p[(long)ps * 2 * g.ask];
        }
        if (bKfast) {
            int kk = tid & 7, c = tid >> 3;
            const float* p = B + (long)(col0 + c) * g.bsr + (kt + kk);
#pragma unroll
            for (int ps = 0; ps < 4; ps++)
                Bs[kk][c + ps * 32] = p[(long)ps * 32 * g.bsr];
        } else {
            int c = tid & 127, kk = tid >> 7;
            const float* p = B + (long)(kt + kk) * g.bsk + (long)(col0 + c) * g.bsr;
#pragma unroll
            for (int ps = 0; ps < 4; ps++)
                Bs[kk + ps * 2][c] = p[(long)ps * 2 * g.bsk];
        }
        __syncthreads();
#pragma unroll
        for (int kk = 0; kk < 8; kk++) {
            float4 a0 = *reinterpret_cast<const float4*>(&As[kk][ty * 4]);
            float4 a1 = *reinterpret_cast<const float4*>(&As[kk][64 + ty * 4]);
            float4 b0 = *reinterpret_cast<const float4*>(&Bs[kk][tx * 4]);
            float4 b1 = *reinterpret_cast<const float4*>(&Bs[kk][64 + tx * 4]);
            float av[8] = {a0.x, a0.y, a0.z, a0.w, a1.x, a1.y, a1.z, a1.w};
            float bv[8] = {b0.x, b0.y, b0.z, b0.w, b1.x, b1.y, b1.z, b1.w};
#pragma unroll
            for (int i = 0; i < 8; i++)
#pragma unroll
                for (int j = 0; j < 8; j++) acc[i][j] += av[i] * bv[j];
        }
        __syncthreads();
    }

    float* C = g.C + (long)b * g.cbs;
    const float* Dm = g.Dm ? (g.Dm + (long)b * g.dbs) : (const float*)0;
#pragma unroll
    for (int i = 0; i < 8; i++) {
        int r = row0 + ((i < 4) ? (ty * 4 + i) : (64 + ty * 4 + (i - 4)));
#pragma unroll
        for (int j = 0; j < 8; j++) {
            int c = col0 + ((j < 4) ? (tx * 4 + j) : (64 + tx * 4 + (j - 4)));
            long off = (long)r * g.csr + (long)c * g.csc;
            float val = g.alpha * acc[i][j];
            if (Dm) val += g.beta * Dm[off];
            C[off] = val;
        }
    }
}

// ------------------------- elementwise kernels ------------------------------
__device__ __forceinline__ float sigf(float x) { return 1.f / (1.f + expf(-x)); }

__global__ void k_init(const float* w0, const float* w1, const float* w2) {
    int row = blockIdx.x;          // NMAT*512 rows
    int m = row >> 9;
    int w = m >> 3;
    int bh = m & 7;
    int r = row & 511;
    const float* src = (w == 0 ? w0 : (w == 1 ? w1 : w2)) + (long)bh * MSZ + (long)r * 512;
    float* wm = &g_wm[m][r * 512];
    float* wc = &g_wc[m][r * 512];
    float* dm = &g_dm[m][r * 512];
    int t = threadIdx.x;
    float ss = 0.f;
#pragma unroll
    for (int j = 0; j < 4; j++) {
        int c = t + j * 128;
        float v = src[c];
        wm[c] = v; wc[c] = v; dm[c] = 0.f;
        ss += v * v;
    }
    __shared__ float red[128];
    red[t] = ss; __syncthreads();
    for (int s = 64; s > 0; s >>= 1) { if (t < s) red[t] += red[t + s]; __syncthreads(); }
    if (t == 0) g_wnorm[m][r] = sqrtf(red[0]);
}

__global__ void k_ew1(const float* lr1, int cbase) {
    int idx = blockIdx.x * 256 + threadIdx.x;
    int t = idx & (CS - 1);
    int bh = idx / (DI * CS);
    float gba = g_gba[idx];
    float hbm = g_hbm[idx];
    float dh  = g_dhid[idx];
    float sg = sigf(gba);
    float sil = gba * sg;
    float hidden = sil * hbm;
    float l1 = lr1[(long)bh * TT + cbase + t];
    g_hl1[idx]  = hidden * l1;
    g_dhbm[idx] = dh * sil;
    float dgate = dh * hbm;
    g_dgba[idx] = dgate * sg * (1.f + gba * (1.f - sg));
    float g0v = g_g0[idx];
    float hv  = g_hh[idx];
    float sq = sigf(g0v);
    g_gh[idx] = g0v * sq * hv;
}

__global__ void k_ew2(const float* kin, const float* lr0, const float* lr2, int cbase) {
    int idx = blockIdx.x * 256 + threadIdx.x;
    int c = idx & (DD - 1);
    int t = (idx >> 9) & (CS - 1);
    int bh = idx / (CS * DD);
    float kv = kin[(long)bh * TT * DD + (long)(cbase + t) * DD + c];
    float l0 = lr0[(long)bh * TT + cbase + t];
    float l2 = lr2[(long)bh * TT + cbase + t];
    g_kl0[idx] = kv * l0;
    g_kl2[idx] = kv * l2;
}

__global__ void k_ewfwd() {
    int idx = blockIdx.x * 256 + threadIdx.x;
    float g0v = g_g0[idx];
    float hv  = g_hh[idx];
    float sq = sigf(g0v);
    g_gh[idx] = g0v * sq * hv;
}

__global__ void k_scalars(const float* mom, const float* mlt, int cbase) {
    int bh = blockIdx.x;
    int t = threadIdx.x;  // 256
    __shared__ float r1[256], r2[256];
    r1[t] = mom[(long)bh * TT + cbase + t];
    r2[t] = mlt[(long)bh * TT + cbase + t];
    __syncthreads();
    for (int s = 128; s > 0; s >>= 1) {
        if (t < s) { r1[t] += r1[t + s]; r2[t] += r2[t + s]; }
        __syncthreads();
    }
    if (t == 0) { g_mi[bh] = r1[0] * (1.f / CS); g_mli[bh] = r2[0] * (1.f / CS); }
}

__global__ void k_dwupd() {
    int idx = blockIdx.x * 256 + threadIdx.x;  // NMAT*MSZ exact
    int m = idx >> 18;                          // MSZ = 2^18
    int bh = m & 7;
    float* dmf = &g_dm[0][0];
    const float* dwf = &g_dw[0][0];
    float v = dwf[idx] + dmf[idx] * g_mi[bh];
    dmf[idx] = v;
}

__global__ void k_norm24() {
    int m = blockIdx.x;
    int t = threadIdx.x;  // 256
    const float* p = g_dm[m];
    float s = 0.f;
    for (int i = t; i < MSZ; i += 256) { float v = p[i]; s += v * v; }
    __shared__ float red[256];
    red[t] = s; __syncthreads();
    for (int st = 128; st > 0; st >>= 1) { if (t < st) red[t] += red[t + st]; __syncthreads(); }
    if (t == 0) g_rns[m] = 1.f / (sqrtf(red[0]) + 1e-7f);
}

__global__ void k_xscale() {
    int idx = blockIdx.x * 256 + threadIdx.x;
    int m = idx >> 18;
    (&g_X0[0][0])[idx] = (&g_dm[0][0])[idx] * g_rns[m];
}

__global__ void k_wupd(const float* X) {
    int row = blockIdx.x;
    int m = row >> 9;
    int bh = m & 7;
    int r = row & 511;
    const float* x = X + (long)m * MSZ + (long)r * 512;
    float* wm = &g_wm[m][r * 512];
    float ml = g_mli[bh];
    int t = threadIdx.x;  // 128
    float vals[4];
    float ss = 0.f;
#pragma unroll
    for (int j = 0; j < 4; j++) {
        int c = t + j * 128;
        float v = wm[c] + x[c] * ml;
        wm[c] = v; vals[j] = v;
        ss += v * v;
    }
    __shared__ float red[128];
    red[t] = ss; __syncthreads();
    for (int s = 64; s > 0; s >>= 1) { if (t < s) red[t] += red[t + s]; __syncthreads(); }
    float scale = g_wnorm[m][r] / (sqrtf(red[0]) + 1e-5f);
#pragma unroll
    for (int j = 0; j < 4; j++) {
        int c = t + j * 128;
        g_wc[m][r * 512 + c] = vals[j] * scale;
    }
}

// ------------------------- host orchestration -------------------------------
static void launch_gemm(const float* A, int asr, int ask, long abs_,
                        const float* B, int bsr, int bsk, long bbs,
                        float* C, int csr, int csc, long cbs,
                        const float* Dm, long dbs,
                        int M, int N, int K, float alpha, float beta, int batch) {
    GArgs g;
    g.A = A; g.asr = asr; g.ask = ask; g.abs_ = abs_;
    g.B = B; g.bsr = bsr; g.bsk = bsk; g.bbs = bbs;
    g.C = C; g.csr = csr; g.csc = csc; g.cbs = cbs;
    g.Dm = Dm; g.dbs = dbs;
    g.K = K; g.alpha = alpha; g.beta = beta;
    dim3 grid(N / 128, M / 128, batch);
    gemm_k<<<grid, 256>>>(g);
}

static const float NSC[5][3] = {
    {4.0848f, -6.8946f, 2.927f},
    {3.9505f, -6.3029f, 2.6377f},
    {3.7418f, -5.5913f, 2.3037f},
    {2.8769f, -3.1427f, 1.2046f},
    {2.8366f, -3.0525f, 1.2012f}};

extern "C" void kernel_launch(void* const* d_in, const int* in_sizes, int n_in,
                              void* d_out, int out_size) {
    const float* w0  = (const float*)d_in[0];
    const float* w1  = (const float*)d_in[1];
    const float* w2  = (const float*)d_in[2];
    const float* q   = (const float*)d_in[3];
    const float* kin = (const float*)d_in[4];
    const float* v   = (const float*)d_in[5];
    const float* lr0 = (const float*)d_in[6];
    const float* lr1 = (const float*)d_in[7];
    const float* lr2 = (const float*)d_in[8];
    const float* mom = (const float*)d_in[9];
    const float* mlt = (const float*)d_in[10];
    float* out = (float*)d_out;

    float *p_wc, *p_dw, *p_X0, *p_X1, *p_Ab, *p_Bb;
    float *p_gba, *p_hbm, *p_hh, *p_g0, *p_dhid, *p_gh, *p_hl1, *p_dhbm, *p_dgba, *p_kl0, *p_kl2;
    cudaGetSymbolAddress((void**)&p_wc, g_wc);
    cudaGetSymbolAddress((void**)&p_dw, g_dw);
    cudaGetSymbolAddress((void**)&p_X0, g_X0);
    cudaGetSymbolAddress((void**)&p_X1, g_X1);
    cudaGetSymbolAddress((void**)&p_Ab, g_Ab);
    cudaGetSymbolAddress((void**)&p_Bb, g_Bb);
    cudaGetSymbolAddress((void**)&p_gba, g_gba);
    cudaGetSymbolAddress((void**)&p_hbm, g_hbm);
    cudaGetSymbolAddress((void**)&p_hh, g_hh);
    cudaGetSymbolAddress((void**)&p_g0, g_g0);
    cudaGetSymbolAddress((void**)&p_dhid, g_dhid);
    cudaGetSymbolAddress((void**)&p_gh, g_gh);
    cudaGetSymbolAddress((void**)&p_hl1, g_hl1);
    cudaGetSymbolAddress((void**)&p_dhbm, g_dhbm);
    cudaGetSymbolAddress((void**)&p_dgba, g_dgba);
    cudaGetSymbolAddress((void**)&p_kl0, g_kl0);
    cudaGetSymbolAddress((void**)&p_kl2, g_kl2);

    const long WBS = (long)BH * MSZ;         // per-weight block of 8 matrices
    const long IBS = (long)DI * CS;          // intermediate batch stride
    const long TDS = (long)TT * DD;          // token-tensor batch stride
    const long KBS = (long)CS * DD;

    k_init<<<NMAT * 512, 128>>>(w0, w1, w2);

    for (int ci = 0; ci < NCHUNK; ci++) {
        int cb = ci * CS;
        const float* kcb = kin + (long)cb * DD;
        const float* qcb = q + (long)cb * DD;
        const float* vcb = v + (long)cb * DD;

        // gba = w0c @ k^T ; hbm = w2c @ k^T ; h = w2c @ q^T ; g0 = w0c @ q^T
        launch_gemm(p_wc,            DD, 1, MSZ, kcb, DD, 1, TDS, p_gba, CS, 1, IBS, 0, 0, DI, CS, DD, 1.f, 0.f, BH);
        launch_gemm(p_wc + 2 * WBS,  DD, 1, MSZ, kcb, DD, 1, TDS, p_hbm, CS, 1, IBS, 0, 0, DI, CS, DD, 1.f, 0.f, BH);
        launch_gemm(p_wc + 2 * WBS,  DD, 1, MSZ, qcb, DD, 1, TDS, p_hh,  CS, 1, IBS, 0, 0, DI, CS, DD, 1.f, 0.f, BH);
        launch_gemm(p_wc,            DD, 1, MSZ, qcb, DD, 1, TDS, p_g0,  CS, 1, IBS, 0, 0, DI, CS, DD, 1.f, 0.f, BH);
        // dhidden = w1c^T @ v^T
        launch_gemm(p_wc + 1 * WBS,  1, DI, MSZ, vcb, DD, 1, TDS, p_dhid, CS, 1, IBS, 0, 0, DI, CS, DD, 1.f, 0.f, BH);

        k_ew1<<<EW1_N / 256, 256>>>(lr1, cb);
        k_ew2<<<EW2_N / 256, 256>>>(kin, lr0, lr2, cb);

        // chunk_out = w1c @ (gate*h) -> written straight into d_out[bh, cb.., :]
        launch_gemm(p_wc + 1 * WBS, DI, 1, MSZ, p_gh, 1, CS, IBS,
                    out + (long)cb * DD, 1, DD, TDS, 0, 0, DD, CS, DI, 1.f, 0.f, BH);
        // dw1 = v^T @ (hidden^T * l1)
        launch_gemm(vcb, 1, DD, TDS, p_hl1, CS, 1, IBS,
                    p_dw + 1 * WBS, DI, 1, MSZ, 0, 0, DD, DI, CS, 1.f, 0.f, BH);
        // dw0 = dgba @ (k*l0)
        launch_gemm(p_dgba, CS, 1, IBS, p_kl0, 1, DD, KBS,
                    p_dw, DD, 1, MSZ, 0, 0, DI, DD, CS, 1.f, 0.f, BH);
        // dw2 = dhbm @ (k*l2)
        launch_gemm(p_dhbm, CS, 1, IBS, p_kl2, 1, DD, KBS,
                    p_dw + 2 * WBS, DD, 1, MSZ, 0, 0, DI, DD, CS, 1.f, 0.f, BH);

        k_scalars<<<BH, 256>>>(mom, mlt, cb);
        k_dwupd<<<NMAT * MSZ / 256, 256>>>();
        k_norm24<<<NMAT, 256>>>();
        k_xscale<<<NMAT * MSZ / 256, 256>>>();

        // Newton-Schulz (5 iters, 24 matrices). A and A@A are exactly symmetric.
        float* Xa = p_X0;
        float* Xb = p_X1;
        for (int it = 0; it < 5; it++) {
            float a = NSC[it][0], bcoef = NSC[it][1], ccoef = NSC[it][2];
            // A = X @ X^T
            launch_gemm(Xa, 512, 1, MSZ, Xa, 512, 1, MSZ, p_Ab, 512, 1, MSZ,
                        0, 0, 512, 512, 512, 1.f, 0.f, NMAT);
            // B = b*A + c*(A@A)   (A symmetric -> NT form)
            launch_gemm(p_Ab, 512, 1, MSZ, p_Ab, 512, 1, MSZ, p_Bb, 512, 1, MSZ,
                        p_Ab, MSZ, 512, 512, 512, ccoef, bcoef, NMAT);
            // X' = a*X + B@X
            launch_gemm(p_Bb, 512, 1, MSZ, Xa, 1, 512, MSZ, Xb, 512, 1, MSZ,
                        Xa, MSZ, 512, 512, 512, 1.f, a, NMAT);
            float* tmp = Xa; Xa = Xb; Xb = tmp;
        }

        k_wupd<<<NMAT * 512, 128>>>(Xa);
    }

    // final forward-only chunk with the last normalized weights
    {
        int cb = NCHUNK * CS;
        const float* qcb = q + (long)cb * DD;
        launch_gemm(p_wc + 2 * WBS, DD, 1, MSZ, qcb, DD, 1, TDS, p_hh, CS, 1, IBS, 0, 0, DI, CS, DD, 1.f, 0.f, BH);
        launch_gemm(p_wc,           DD, 1, MSZ, qcb, DD, 1, TDS, p_g0, CS, 1, IBS, 0, 0, DI, CS, DD, 1.f, 0.f, BH);
        k_ewfwd<<<EW1_N / 256, 256>>>();
        launch_gemm(p_wc + 1 * WBS, DI, 1, MSZ, p_gh, 1, CS, IBS,
                    out + (long)cb * DD, 1, DD, TDS, 0, 0, DD, CS, DI, 1.f, 0.f, BH);
    }
}

// round 5
// speedup vs baseline: 1.8089x; 1.8089x over previous
#include <cuda_runtime.h>
#include <cuda_bf16.h>
#include <math.h>
#include <stdint.h>

// ---------------------------------------------------------------------------
// LaCT SWIGLU fast-weight attention — mma.sync bf16-split-3 GEMM engine.
// (tcgen05 is unavailable: harness PTX targets compute_103, not 103a.)
// C = alpha * sum_k A(r,k)B(c,k) (+ beta*Dm), A,B as bf16 (hi,lo) K-major
// planes; AhiBhi + AhiBlo + AloBhi accumulated in fp32 via HMMA.
// ---------------------------------------------------------------------------

#define BH 8
#define TT 4096
#define DD 512
#define DI 512
#define CS 256
#define NCHUNK 15
#define NMAT 24
#define MSZ (512 * 512)
#define MAXB 24
// smem: 2 stages x 4 planes x 128 rows x 40 halves(pad) x 2B = 81920
#define AST 40
#define PLANE_H (128 * AST)                  // halves per plane (5120)
#define STAGE_H (4 * PLANE_H)                // halves per stage (20480)
#define SMEM_TOTAL (2 * STAGE_H * 2)         // bytes (81920)

static constexpr long NM_  = (long)NMAT * MSZ;   // 6291456
static constexpr long W1M_ = 8L * MSZ;
static constexpr long CHB  = (long)CS * DD;      // per-bh chunk plane (131072)
static constexpr long CHT  = (long)BH * CHB;     // total chunk plane (1048576)
static constexpr long TDSl = (long)TT * DD;

// fp32 heap offsets
static constexpr long F_WM = 0, F_WC = NM_, F_DM = 2 * NM_, F_DW = 3 * NM_,
                      F_X0 = 4 * NM_, F_X1 = 5 * NM_, F_AB = 6 * NM_, F_BB = 7 * NM_;
static constexpr long F_GBA = 8 * NM_, F_HBM = F_GBA + CHT, F_HH = F_HBM + CHT,
                      F_G0 = F_HH + CHT, F_DHID = F_G0 + CHT, F_GH = F_DHID + CHT,
                      F_KL0 = F_GH + CHT, F_KL2 = F_KL0 + CHT;
static constexpr long F_WNORM = F_KL2 + CHT, F_MI = F_WNORM + NMAT * 512L,
                      F_MLI = F_MI + 8, F_RNS = F_MLI + 8, F_TOT = F_RNS + NMAT;
__device__ float g_f[F_TOT];

// bf16 heap offsets
static constexpr long H_WCH = 0, H_WCL = NM_,
                      H_W1TH = 2 * NM_, H_W1TL = H_W1TH + W1M_,
                      H_XH = H_W1TL + W1M_, H_XL = H_XH + NM_,
                      H_XTH = H_XL + NM_, H_XTL = H_XTH + NM_,
                      H_AH = H_XTL + NM_, H_AL = H_AH + NM_,
                      H_BH = H_AL + NM_, H_BL = H_BH + NM_;
static constexpr long H_KH = H_BL + NM_, H_KL = H_KH + CHT, H_QH = H_KL + CHT,
                      H_QL = H_QH + CHT, H_VH = H_QL + CHT, H_VL = H_VH + CHT,
                      H_VTH = H_VL + CHT, H_VTL = H_VTH + CHT,
                      H_K0H = H_VTL + CHT, H_K0L = H_K0H + CHT,
                      H_K2H = H_K0L + CHT, H_K2L = H_K2H + CHT,
                      H_GTH = H_K2L + CHT, H_GTL = H_GTH + CHT,
                      H_HLH = H_GTL + CHT, H_HLL = H_HLH + CHT,
                      H_DGH = H_HLL + CHT, H_DGL = H_DGH + CHT,
                      H_DBH = H_DGL + CHT, H_DBL = H_DBH + CHT,
                      H_TOT = H_DBL + CHT;
__device__ __nv_bfloat16 g_h[H_TOT];

// ------------------------- helpers -----------------------------------------
__device__ __forceinline__ uint32_t smem_u32(const void* p) {
    uint32_t a;
    asm("{ .reg .u64 t; cvta.to.shared.u64 t, %1; cvt.u32.u64 %0, t; }" : "=r"(a) : "l"(p));
    return a;
}
__device__ __forceinline__ void cp16(uint32_t dst, const void* src) {
    asm volatile("cp.async.cg.shared.global [%0], [%1], 16;" :: "r"(dst), "l"(src));
}
__device__ __forceinline__ void cp_commit() {
    asm volatile("cp.async.commit_group;" ::: "memory");
}
template <int N>
__device__ __forceinline__ void cp_wait() {
    asm volatile("cp.async.wait_group %0;" :: "n"(N) : "memory");
}
__device__ __forceinline__ void ldm4(uint32_t* f, uint32_t addr) {
    asm volatile("ldmatrix.sync.aligned.m8n8.x4.shared.b16 {%0,%1,%2,%3}, [%4];"
                 : "=r"(f[0]), "=r"(f[1]), "=r"(f[2]), "=r"(f[3]) : "r"(addr));
}
__device__ __forceinline__ void mma16816(float* c, const uint32_t* a, const uint32_t* b) {
    asm volatile("mma.sync.aligned.m16n8k16.row.col.f32.bf16.bf16.f32 "
                 "{%0,%1,%2,%3}, {%4,%5,%6,%7}, {%8,%9}, {%0,%1,%2,%3};"
                 : "+f"(c[0]), "+f"(c[1]), "+f"(c[2]), "+f"(c[3])
                 : "r"(a[0]), "r"(a[1]), "r"(a[2]), "r"(a[3]), "r"(b[0]), "r"(b[1]));
}
__device__ __forceinline__ void wsplit(__nv_bfloat16* H, __nv_bfloat16* L, long i, float v) {
    __nv_bfloat16 h = __float2bfloat16(v);
    H[i] = h;
    L[i] = __float2bfloat16(v - __bfloat162float(h));
}
__device__ __forceinline__ float sigf(float x) { return 1.f / (1.f + expf(-x)); }

// ------------------------- GEMM kernel --------------------------------------
struct TArgs {
    const __nv_bfloat16 *Ah[MAXB], *Al[MAXB], *Bh[MAXB], *Bl[MAXB];
    float* C[MAXB];
    const float* Dm[MAXB];
    __nv_bfloat16 *OH[MAXB], *OL[MAXB];
    int K, csr, csc, hasD, hasO;
    float alpha, beta;
};

// Load a 128-row x 32-half slab of a K-major plane into padded smem (AST=40).
__device__ __forceinline__ void ldplane(uint32_t smbase, const __nv_bfloat16* g,
                                        int r0, int Kd, int kt, int tid) {
#pragma unroll
    for (int i = 0; i < 2; i++) {
        int idx = tid + i * 256;         // 0..511 chunks of 16B
        int row = idx >> 2;
        int ch = (idx & 3) << 3;         // half offset 0/8/16/24
        const __nv_bfloat16* src = g + (long)(r0 + row) * Kd + kt + ch;
        cp16(smbase + (uint32_t)(row * AST + ch) * 2u, src);
    }
}

__global__ __launch_bounds__(256, 1) void tgemm(const __grid_constant__ TArgs g) {
    extern __shared__ __nv_bfloat16 smh[];
    uint32_t smb = smem_u32(smh);

    const int tid = threadIdx.x;
    const int lane = tid & 31;
    const int wid = tid >> 5;
    const int wm = wid >> 2;     // 0..1 row group (64 rows)
    const int wn = wid & 3;      // 0..3 col group (32 cols)
    const int z = blockIdx.z;
    const int row0 = blockIdx.y * 128, col0 = blockIdx.x * 128;
    const __nv_bfloat16* Ah = g.Ah[z];
    const __nv_bfloat16* Al = g.Al[z];
    const __nv_bfloat16* Bh = g.Bh[z];
    const __nv_bfloat16* Bl = g.Bl[z];
    const int Kd = g.K;
    const int nslab = Kd >> 5;

    float acc[4][4][4];
#pragma unroll
    for (int i = 0; i < 4; i++)
#pragma unroll
        for (int j = 0; j < 4; j++)
#pragma unroll
            for (int r = 0; r < 4; r++) acc[i][j][r] = 0.f;

    // ldmatrix per-lane row/col components
    const int lrow = lane & 15;
    const int lcol = (lane >> 4) << 3;   // 0 or 8 halves

    // prologue: stage 0
    {
        uint32_t sb = smb;
        ldplane(sb,                      Ah, row0, Kd, 0, tid);
        ldplane(sb + PLANE_H * 2,        Al, row0, Kd, 0, tid);
        ldplane(sb + 2 * PLANE_H * 2,    Bh, col0, Kd, 0, tid);
        ldplane(sb + 3 * PLANE_H * 2,    Bl, col0, Kd, 0, tid);
        cp_commit();
    }

    for (int s = 0; s < nslab; s++) {
        if (s + 1 < nslab) {
            uint32_t sb = smb + (uint32_t)(((s + 1) & 1) * STAGE_H) * 2u;
            int kt = (s + 1) << 5;
            ldplane(sb,                   Ah, row0, Kd, kt, tid);
            ldplane(sb + PLANE_H * 2,     Al, row0, Kd, kt, tid);
            ldplane(sb + 2 * PLANE_H * 2, Bh, col0, Kd, kt, tid);
            ldplane(sb + 3 * PLANE_H * 2, Bl, col0, Kd, kt, tid);
            cp_commit();
            cp_wait<1>();
        } else {
            cp_wait<0>();
        }
        __syncthreads();

        uint32_t sb = smb + (uint32_t)((s & 1) * STAGE_H) * 2u;
#pragma unroll
        for (int k16 = 0; k16 < 2; k16++) {
            const int kh = k16 * 16 + lcol;
            uint32_t ahf[4][4], alf[4][4], bhf[2][4], blf[2][4];
#pragma unroll
            for (int mt = 0; mt < 4; mt++) {
                int ar = wm * 64 + mt * 16 + lrow;
                uint32_t off = (uint32_t)(ar * AST + kh) * 2u;
                ldm4(ahf[mt], sb + off);
                ldm4(alf[mt], sb + PLANE_H * 2 + off);
            }
#pragma unroll
            for (int pr = 0; pr < 2; pr++) {
                int br = wn * 32 + pr * 16 + lrow;
                uint32_t off = (uint32_t)(br * AST + kh) * 2u;
                ldm4(bhf[pr], sb + 2 * PLANE_H * 2 + off);
                ldm4(blf[pr], sb + 3 * PLANE_H * 2 + off);
            }
#pragma unroll
            for (int mt = 0; mt < 4; mt++) {
#pragma unroll
                for (int nt = 0; nt < 4; nt++) {
                    int pr = nt >> 1, hi = nt & 1;
                    uint32_t bh2[2] = {bhf[pr][hi], bhf[pr][hi + 2]};
                    uint32_t bl2[2] = {blf[pr][hi], blf[pr][hi + 2]};
                    mma16816(acc[mt][nt], ahf[mt], bh2);
                    mma16816(acc[mt][nt], ahf[mt], bl2);
                    mma16816(acc[mt][nt], alf[mt], bh2);
                }
            }
        }
        __syncthreads();
    }

    // epilogue
    float* C = g.C[z];
    const float* Dm = g.Dm[z];
    __nv_bfloat16* oh = g.OH[z];
    __nv_bfloat16* ol = g.OL[z];
    const int gr = lane >> 2, gc = (lane & 3) * 2;
#pragma unroll
    for (int mt = 0; mt < 4; mt++) {
#pragma unroll
        for (int nt = 0; nt < 4; nt++) {
#pragma unroll
            for (int rg = 0; rg < 4; rg++) {
                int r = row0 + wm * 64 + mt * 16 + gr + ((rg >> 1) << 3);
                int c = col0 + wn * 32 + nt * 8 + gc + (rg & 1);
                long off = (long)r * g.csr + (long)c * g.csc;
                float val = g.alpha * acc[mt][nt][rg];
                if (g.hasD) val += g.beta * Dm[off];
                C[off] = val;
                if (g.hasO) {
                    __nv_bfloat16 h = __float2bfloat16(val);
                    oh[off] = h;
                    ol[off] = __float2bfloat16(val - __bfloat162float(h));
                }
            }
        }
    }
}

// ------------------------- transpose/split ---------------------------------
struct TSArgs {
    const float* src; long sbs; int srows, scols;
    __nv_bfloat16 *pH, *pL; long pbs;
    __nv_bfloat16 *tH, *tL; long tbs;
};
__global__ void k_tsplit(const __grid_constant__ TSArgs a) {
    __shared__ float tile[32][33];
    int z = blockIdx.z;
    const float* S = a.src + (long)z * a.sbs;
    int c0 = blockIdx.x * 32, r0 = blockIdx.y * 32;
    int tx = threadIdx.x, ty = threadIdx.y;
#pragma unroll
    for (int j = 0; j < 4; j++) {
        int r = r0 + ty + j * 8;
        float v = S[(long)r * a.scols + c0 + tx];
        tile[ty + j * 8][tx] = v;
        if (a.pH) {
            long o = (long)z * a.pbs + (long)r * a.scols + c0 + tx;
            wsplit(a.pH, a.pL, o, v);
        }
    }
    __syncthreads();
    if (a.tH) {
#pragma unroll
        for (int j = 0; j < 4; j++) {
            int c = c0 + ty + j * 8;
            float v = tile[tx][ty + j * 8];
            long o = (long)z * a.tbs + (long)c * a.srows + r0 + tx;
            wsplit(a.tH, a.tL, o, v);
        }
    }
}

// ------------------------- elementwise kernels ------------------------------
__global__ void k_init(const float* w0, const float* w1, const float* w2) {
    int row = blockIdx.x;
    int m = row >> 9, w = m >> 3, bh = m & 7, r = row & 511;
    const float* src = (w == 0 ? w0 : (w == 1 ? w1 : w2)) + (long)bh * MSZ + (long)r * 512;
    long mo = (long)m * MSZ + (long)r * 512;
    int t = threadIdx.x;
    float ss = 0.f;
#pragma unroll
    for (int j = 0; j < 4; j++) {
        int c = t + j * 128;
        float v = src[c];
        g_f[F_WM + mo + c] = v;
        g_f[F_WC + mo + c] = v;
        g_f[F_DM + mo + c] = 0.f;
        wsplit(g_h + H_WCH, g_h + H_WCL, mo + c, v);
        ss += v * v;
    }
    __shared__ float red[128];
    red[t] = ss; __syncthreads();
    for (int s = 64; s > 0; s >>= 1) { if (t < s) red[t] += red[t + s]; __syncthreads(); }
    if (t == 0) g_f[F_WNORM + (long)m * 512 + r] = sqrtf(red[0]);
}

__global__ void k_splitKQ(const float* kin, const float* q, int cbase) {
    long idx = blockIdx.x * 256L + threadIdx.x;
    int d = idx & 511;
    int t = (int)((idx >> 9) & 255);
    int bh = (int)(idx >> 17);
    long so = (long)bh * TDSl + (long)(cbase + t) * DD + d;
    wsplit(g_h + H_KH, g_h + H_KL, idx, kin[so]);
    wsplit(g_h + H_QH, g_h + H_QL, idx, q[so]);
}

__global__ void k_ew1(const float* lr1, int cbase) {
    long idx = blockIdx.x * 256L + threadIdx.x;
    int t = idx & (CS - 1);
    int bh = (int)(idx >> 17);
    float gba = g_f[F_GBA + idx], hbm = g_f[F_HBM + idx], dh = g_f[F_DHID + idx];
    float sg = sigf(gba), sil = gba * sg;
    float hidden = sil * hbm;
    float l1 = lr1[(long)bh * TT + cbase + t];
    wsplit(g_h + H_HLH, g_h + H_HLL, idx, hidden * l1);
    wsplit(g_h + H_DBH, g_h + H_DBL, idx, dh * sil);
    float dgate = dh * hbm;
    wsplit(g_h + H_DGH, g_h + H_DGL, idx, dgate * sg * (1.f + gba * (1.f - sg)));
    float g0v = g_f[F_G0 + idx], hv = g_f[F_HH + idx];
    g_f[F_GH + idx] = g0v * sigf(g0v) * hv;
}

__global__ void k_ew2(const float* kin, const float* lr0, const float* lr2, int cbase) {
    long idx = blockIdx.x * 256L + threadIdx.x;
    int d = idx & 511;
    int t = (int)((idx >> 9) & 255);
    int bh = (int)(idx >> 17);
    float kv = kin[(long)bh * TDSl + (long)(cbase + t) * DD + d];
    g_f[F_KL0 + idx] = kv * lr0[(long)bh * TT + cbase + t];
    g_f[F_KL2 + idx] = kv * lr2[(long)bh * TT + cbase + t];
}

__global__ void k_ewfwd() {
    long idx = blockIdx.x * 256L + threadIdx.x;
    float g0v = g_f[F_G0 + idx], hv = g_f[F_HH + idx];
    g_f[F_GH + idx] = g0v * sigf(g0v) * hv;
}

__global__ void k_scalars(const float* mom, const float* mlt, int cbase) {
    int bh = blockIdx.x;
    int t = threadIdx.x;
    __shared__ float r1[256], r2[256];
    r1[t] = mom[(long)bh * TT + cbase + t];
    r2[t] = mlt[(long)bh * TT + cbase + t];
    __syncthreads();
    for (int s = 128; s > 0; s >>= 1) {
        if (t < s) { r1[t] += r1[t + s]; r2[t] += r2[t + s]; }
        __syncthreads();
    }
    if (t == 0) { g_f[F_MI + bh] = r1[0] * (1.f / CS); g_f[F_MLI + bh] = r2[0] * (1.f / CS); }
}

__global__ void k_dwupd() {
    long idx = blockIdx.x * 256L + threadIdx.x;
    int m = (int)(idx >> 18);
    int bh = m & 7;
    g_f[F_DM + idx] = g_f[F_DW + idx] + g_f[F_DM + idx] * g_f[F_MI + bh];
}

__global__ void k_norm24() {
    int m = blockIdx.x;
    int t = threadIdx.x;
    const float* p = g_f + F_DM + (long)m * MSZ;
    float s = 0.f;
    for (int i = t; i < MSZ; i += 256) { float v = p[i]; s += v * v; }
    __shared__ float red[256];
    red[t] = s; __syncthreads();
    for (int st = 128; st > 0; st >>= 1) { if (t < st) red[t] += red[t + st]; __syncthreads(); }
    if (t == 0) g_f[F_RNS + m] = 1.f / (sqrtf(red[0]) + 1e-7f);
}

__global__ void k_xscale() {
    long idx = blockIdx.x * 256L + threadIdx.x;
    int m = (int)(idx >> 18);
    float v = g_f[F_DM + idx] * g_f[F_RNS + m];
    g_f[F_X0 + idx] = v;
    wsplit(g_h + H_XH, g_h + H_XL, idx, v);
}

__global__ void k_wupd(const float* x) {
    int row = blockIdx.x;
    int m = row >> 9, bh = m & 7, r = row & 511;
    long mo = (long)m * MSZ + (long)r * 512;
    const float* xp = x + mo;
    float ml = g_f[F_MLI + bh];
    int t = threadIdx.x;
    float vals[4];
    float ss = 0.f;
#pragma unroll
    for (int j = 0; j < 4; j++) {
        int c = t + j * 128;
        float v = g_f[F_WM + mo + c] + xp[c] * ml;
        g_f[F_WM + mo + c] = v;
        vals[j] = v;
        ss += v * v;
    }
    __shared__ float red[128];
    red[t] = ss; __syncthreads();
    for (int s = 64; s > 0; s >>= 1) { if (t < s) red[t] += red[t + s]; __syncthreads(); }
    float scale = g_f[F_WNORM + (long)m * 512 + r] / (sqrtf(red[0]) + 1e-5f);
#pragma unroll
    for (int j = 0; j < 4; j++) {
        int c = t + j * 128;
        float w = vals[j] * scale;
        g_f[F_WC + mo + c] = w;
        wsplit(g_h + H_WCH, g_h + H_WCL, mo + c, w);
    }
}

// ------------------------- host orchestration -------------------------------
static void tg(const __nv_bfloat16* Ah, const __nv_bfloat16* Al, long As,
               const __nv_bfloat16* Bh, const __nv_bfloat16* Bl, long Bs,
               float* C, long Cs, int csr, int csc,
               const float* Dm, long Ds,
               __nv_bfloat16* OH, __nv_bfloat16* OL, long Os,
               int M, int N, int K, float alpha, float beta, int batch) {
    TArgs g;
    for (int z = 0; z < batch; z++) {
        g.Ah[z] = Ah + (long)z * As; g.Al[z] = Al + (long)z * As;
        g.Bh[z] = Bh + (long)z * Bs; g.Bl[z] = Bl + (long)z * Bs;
        g.C[z] = C + (long)z * Cs;
        g.Dm[z] = Dm ? Dm + (long)z * Ds : (const float*)0;
        g.OH[z] = OH ? OH + (long)z * Os : (__nv_bfloat16*)0;
        g.OL[z] = OL ? OL + (long)z * Os : (__nv_bfloat16*)0;
    }
    g.K = K; g.csr = csr; g.csc = csc;
    g.alpha = alpha; g.beta = beta;
    g.hasD = Dm ? 1 : 0; g.hasO = OH ? 1 : 0;
    tgemm<<<dim3(N / 128, M / 128, batch), 256, SMEM_TOTAL>>>(g);
}

static void ts(const float* src, long sbs, int srows, int scols,
               __nv_bfloat16* pH, __nv_bfloat16* pL, long pbs,
               __nv_bfloat16* tH, __nv_bfloat16* tL, long tbs, int batch) {
    TSArgs a;
    a.src = src; a.sbs = sbs; a.srows = srows; a.scols = scols;
    a.pH = pH; a.pL = pL; a.pbs = pbs;
    a.tH = tH; a.tL = tL; a.tbs = tbs;
    k_tsplit<<<dim3(scols / 32, srows / 32, batch), dim3(32, 8)>>>(a);
}

static const float NSC[5][3] = {
    {4.0848f, -6.8946f, 2.927f},
    {3.9505f, -6.3029f, 2.6377f},
    {3.7418f, -5.5913f, 2.3037f},
    {2.8769f, -3.1427f, 1.2046f},
    {2.8366f, -3.0525f, 1.2012f}};

extern "C" void kernel_launch(void* const* d_in, const int* in_sizes, int n_in,
                              void* d_out, int out_size) {
    const float* w0  = (const float*)d_in[0];
    const float* w1  = (const float*)d_in[1];
    const float* w2  = (const float*)d_in[2];
    const float* q   = (const float*)d_in[3];
    const float* kin = (const float*)d_in[4];
    const float* v   = (const float*)d_in[5];
    const float* lr0 = (const float*)d_in[6];
    const float* lr1 = (const float*)d_in[7];
    const float* lr2 = (const float*)d_in[8];
    const float* mom = (const float*)d_in[9];
    const float* mlt = (const float*)d_in[10];
    float* out = (float*)d_out;

    static int smset = 0;
    if (!smset) {
        cudaFuncSetAttribute(tgemm, cudaFuncAttributeMaxDynamicSharedMemorySize, SMEM_TOTAL);
        smset = 1;
    }

    float* F;
    __nv_bfloat16* H;
    cudaGetSymbolAddress((void**)&F, g_f);
    cudaGetSymbolAddress((void**)&H, g_h);

    k_init<<<NMAT * 512, 128>>>(w0, w1, w2);
    ts(F + F_WC + 8L * MSZ, MSZ, 512, 512, 0, 0, 0, H + H_W1TH, H + H_W1TL, MSZ, 8);

    for (int ci = 0; ci < NCHUNK; ci++) {
        int cb = ci * CS;

        k_splitKQ<<<(int)(CHT / 256), 256>>>(kin, q, cb);
        ts(v + (long)cb * DD, TDSl, 256, 512,
           H + H_VH, H + H_VL, CHB, H + H_VTH, H + H_VTL, CHB, 8);

        // fwd/bwd activations (batch 8, M=512, N=256, K=512)
        tg(H + H_WCH,             H + H_WCL,             MSZ, H + H_KH, H + H_KL, CHB,
           F + F_GBA, CHB, CS, 1, 0, 0, 0, 0, 0, 512, 256, 512, 1.f, 0.f, 8);
        tg(H + H_WCH + 16L * MSZ, H + H_WCL + 16L * MSZ, MSZ, H + H_KH, H + H_KL, CHB,
           F + F_HBM, CHB, CS, 1, 0, 0, 0, 0, 0, 512, 256, 512, 1.f, 0.f, 8);
        tg(H + H_WCH + 16L * MSZ, H + H_WCL + 16L * MSZ, MSZ, H + H_QH, H + H_QL, CHB,
           F + F_HH, CHB, CS, 1, 0, 0, 0, 0, 0, 512, 256, 512, 1.f, 0.f, 8);
        tg(H + H_WCH,             H + H_WCL,             MSZ, H + H_QH, H + H_QL, CHB,
           F + F_G0, CHB, CS, 1, 0, 0, 0, 0, 0, 512, 256, 512, 1.f, 0.f, 8);
        tg(H + H_W1TH, H + H_W1TL, MSZ, H + H_VH, H + H_VL, CHB,
           F + F_DHID, CHB, CS, 1, 0, 0, 0, 0, 0, 512, 256, 512, 1.f, 0.f, 8);

        k_ew1<<<(int)(CHT / 256), 256>>>(lr1, cb);
        k_ew2<<<(int)(CHT / 256), 256>>>(kin, lr0, lr2, cb);

        ts(F + F_GH, CHB, 512, 256, 0, 0, 0, H + H_GTH, H + H_GTL, CHB, 8);
        ts(F + F_KL0, CHB, 256, 512, 0, 0, 0, H + H_K0H, H + H_K0L, CHB, 8);
        ts(F + F_KL2, CHB, 256, 512, 0, 0, 0, H + H_K2H, H + H_K2L, CHB, 8);

        // chunk_out = w1c @ (gate*h) -> d_out[bh, cb+t, :]
        tg(H + H_WCH + 8L * MSZ, H + H_WCL + 8L * MSZ, MSZ, H + H_GTH, H + H_GTL, CHB,
           out + (long)cb * DD, TDSl, 1, DD, 0, 0, 0, 0, 0, 512, 256, 512, 1.f, 0.f, 8);
        // dw1 = v^T @ (hidden^T * l1)
        tg(H + H_VTH, H + H_VTL, CHB, H + H_HLH, H + H_HLL, CHB,
           F + F_DW + 8L * MSZ, MSZ, 512, 1, 0, 0, 0, 0, 0, 512, 512, 256, 1.f, 0.f, 8);
        // dw0 = dgba @ (k*l0)
        tg(H + H_DGH, H + H_DGL, CHB, H + H_K0H, H + H_K0L, CHB,
           F + F_DW, MSZ, 512, 1, 0, 0, 0, 0, 0, 512, 512, 256, 1.f, 0.f, 8);
        // dw2 = dhbm @ (k*l2)
        tg(H + H_DBH, H + H_DBL, CHB, H + H_K2H, H + H_K2L, CHB,
           F + F_DW + 16L * MSZ, MSZ, 512, 1, 0, 0, 0, 0, 0, 512, 512, 256, 1.f, 0.f, 8);

        k_scalars<<<BH, 256>>>(mom, mlt, cb);
        k_dwupd<<<(int)(NM_ / 256), 256>>>();
        k_norm24<<<NMAT, 256>>>();
        k_xscale<<<(int)(NM_ / 256), 256>>>();
        ts(F + F_X0, MSZ, 512, 512, 0, 0, 0, H + H_XTH, H + H_XTL, MSZ, 24);

        // Newton-Schulz (5 iters, 24 matrices)
        float* Xc = F + F_X0;
        float* Xn = F + F_X1;
        for (int it = 0; it < 5; it++) {
            float aa = NSC[it][0], bb = NSC[it][1], cc = NSC[it][2];
            // A = X @ X^T (exactly symmetric)
            tg(H + H_XH, H + H_XL, MSZ, H + H_XH, H + H_XL, MSZ,
               F + F_AB, MSZ, 512, 1, 0, 0, H + H_AH, H + H_AL, MSZ,
               512, 512, 512, 1.f, 0.f, 24);
            // B = b*A + c*(A@A)  (A symmetric -> NT form)
            tg(H + H_AH, H + H_AL, MSZ, H + H_AH, H + H_AL, MSZ,
               F + F_BB, MSZ, 512, 1, F + F_AB, MSZ, H + H_BH, H + H_BL, MSZ,
               512, 512, 512, cc, bb, 24);
            // X' = a*X + B@X  (NT with B-side = X^T planes)
            tg(H + H_BH, H + H_BL, MSZ, H + H_XTH, H + H_XTL, MSZ,
               Xn, MSZ, 512, 1, Xc, MSZ, H + H_XH, H + H_XL, MSZ,
               512, 512, 512, 1.f, aa, 24);
            ts(Xn, MSZ, 512, 512, 0, 0, 0, H + H_XTH, H + H_XTL, MSZ, 24);
            float* tmp = Xc; Xc = Xn; Xn = tmp;
        }

        k_wupd<<<NMAT * 512, 128>>>(Xc);
        ts(F + F_WC + 8L * MSZ, MSZ, 512, 512, 0, 0, 0, H + H_W1TH, H + H_W1TL, MSZ, 8);
    }

    // final forward-only chunk
    {
        int cb = NCHUNK * CS;
        k_splitKQ<<<(int)(CHT / 256), 256>>>(kin, q, cb);
        tg(H + H_WCH + 16L * MSZ, H + H_WCL + 16L * MSZ, MSZ, H + H_QH, H + H_QL, CHB,
           F + F_HH, CHB, CS, 1, 0, 0, 0, 0, 0, 512, 256, 512, 1.f, 0.f, 8);
        tg(H + H_WCH,             H + H_WCL,             MSZ, H + H_QH, H + H_QL, CHB,
           F + F_G0, CHB, CS, 1, 0, 0, 0, 0, 0, 512, 256, 512, 1.f, 0.f, 8);
        k_ewfwd<<<(int)(CHT / 256), 256>>>();
        ts(F + F_GH, CHB, 512, 256, 0, 0, 0, H + H_GTH, H + H_GTL, CHB, 8);
        tg(H + H_WCH + 8L * MSZ, H + H_WCL + 8L * MSZ, MSZ, H + H_GTH, H + H_GTL, CHB,
           out + (long)cb * DD, TDSl, 1, DD, 0, 0, 0, 0, 0, 512, 256, 512, 1.f, 0.f, 8);
    }
}

// round 8
// speedup vs baseline: 2.1110x; 1.1670x over previous
#include <cuda_runtime.h>
#include <cuda_bf16.h>
#include <math.h>
#include <stdint.h>

// ---------------------------------------------------------------------------
// LaCT SWIGLU fast-weight attention — mma.sync bf16-split-3 GEMM engine v2.2.
// v2.1 (compact group-descriptor params) + FIX: NS X'-GEMM read/write race on
// the X^T planes — B-operand planes are now ping-ponged (XT / XT2) so the
// fused transposed epilogue never overwrites planes other CTAs still read.
// ---------------------------------------------------------------------------

#define BH 8
#define TT 4096
#define DD 512
#define DI 512
#define CS 256
#define NCHUNK 15
#define NMAT 24
#define MSZ (512 * 512)
#define AST 40
#define PLANE_H (128 * AST)
#define STAGE_H (4 * PLANE_H)
#define NSTAGE 3
#define SMEM_TOTAL (NSTAGE * STAGE_H * 2)  // 122880 bytes

static constexpr long NM_  = (long)NMAT * MSZ;
static constexpr long W1M_ = 8L * MSZ;
static constexpr long CHB  = (long)CS * DD;
static constexpr long CHT  = (long)BH * CHB;
static constexpr long TDSl = (long)TT * DD;

// fp32 heap
static constexpr long F_WM = 0, F_WC = NM_, F_DM = 2 * NM_, F_DW = 3 * NM_,
                      F_X0 = 4 * NM_, F_X1 = 5 * NM_, F_AB = 6 * NM_;
static constexpr long F_GBA = 7 * NM_, F_HBM = F_GBA + CHT, F_HH = F_HBM + CHT,
                      F_G0 = F_HH + CHT, F_DHID = F_G0 + CHT, F_GH = F_DHID + CHT,
                      F_KL0 = F_GH + CHT, F_KL2 = F_KL0 + CHT;
static constexpr long F_WNORM = F_KL2 + CHT, F_MI = F_WNORM + NMAT * 512L,
                      F_MLI = F_MI + 8, F_RNS = F_MLI + 8, F_TOT = F_RNS + NMAT;
__device__ __align__(256) float g_f[F_TOT];

// bf16 heap
static constexpr long H_WCH = 0, H_WCL = NM_,
                      H_W1TH = 2 * NM_, H_W1TL = H_W1TH + W1M_,
                      H_XH = H_W1TL + W1M_, H_XL = H_XH + NM_,
                      H_XTH = H_XL + NM_, H_XTL = H_XTH + NM_,
                      H_XT2H = H_XTL + NM_, H_XT2L = H_XT2H + NM_,
                      H_AH = H_XT2L + NM_, H_AL = H_AH + NM_,
                      H_BH = H_AL + NM_, H_BL = H_BH + NM_;
static constexpr long H_KH = H_BL + NM_, H_KL = H_KH + CHT, H_QH = H_KL + CHT,
                      H_QL = H_QH + CHT, H_VH = H_QL + CHT, H_VL = H_VH + CHT,
                      H_VTH = H_VL + CHT, H_VTL = H_VTH + CHT,
                      H_K0H = H_VTL + CHT, H_K0L = H_K0H + CHT,
                      H_K2H = H_K0L + CHT, H_K2L = H_K2H + CHT,
                      H_GTH = H_K2L + CHT, H_GTL = H_GTH + CHT,
                      H_HLH = H_GTL + CHT, H_HLL = H_HLH + CHT,
                      H_DGH = H_HLL + CHT, H_DGL = H_DGH + CHT,
                      H_DBH = H_DGL + CHT, H_DBL = H_DBH + CHT,
                      H_TOT = H_DBL + CHT;
__device__ __align__(256) __nv_bfloat16 g_h[H_TOT];

typedef __nv_bfloat16 bf;

// ------------------------- helpers -----------------------------------------
__device__ __forceinline__ uint32_t smem_u32(const void* p) {
    uint32_t a;
    asm("{ .reg .u64 t; cvta.to.shared.u64 t, %1; cvt.u32.u64 %0, t; }" : "=r"(a) : "l"(p));
    return a;
}
__device__ __forceinline__ void cp16(uint32_t dst, const void* src) {
    asm volatile("cp.async.cg.shared.global [%0], [%1], 16;" :: "r"(dst), "l"(src));
}
__device__ __forceinline__ void cp_commit() {
    asm volatile("cp.async.commit_group;" ::: "memory");
}
template <int N>
__device__ __forceinline__ void cp_wait() {
    asm volatile("cp.async.wait_group %0;" :: "n"(N) : "memory");
}
__device__ __forceinline__ void ldm4(uint32_t* f, uint32_t addr) {
    asm volatile("ldmatrix.sync.aligned.m8n8.x4.shared.b16 {%0,%1,%2,%3}, [%4];"
                 : "=r"(f[0]), "=r"(f[1]), "=r"(f[2]), "=r"(f[3]) : "r"(addr));
}
__device__ __forceinline__ void mma16816(float* c, const uint32_t* a, const uint32_t* b) {
    asm volatile("mma.sync.aligned.m16n8k16.row.col.f32.bf16.bf16.f32 "
                 "{%0,%1,%2,%3}, {%4,%5,%6,%7}, {%8,%9}, {%0,%1,%2,%3};"
                 : "+f"(c[0]), "+f"(c[1]), "+f"(c[2]), "+f"(c[3])
                 : "r"(a[0]), "r"(a[1]), "r"(a[2]), "r"(a[3]), "r"(b[0]), "r"(b[1]));
}
__device__ __forceinline__ void wsplit(bf* H, bf* L, long i, float v) {
    bf h = __float2bfloat16(v);
    H[i] = h;
    L[i] = __float2bfloat16(v - __bfloat162float(h));
}
__device__ __forceinline__ float sigf(float x) { return 1.f / (1.f + expf(-x)); }

// ------------------------- GEMM kernel --------------------------------------
struct GD {
    const bf *Ah, *Al, *Bh, *Bl;
    float* C;
    const float* Dm;
    bf *OH, *OL, *OTH, *OTL;
    long As, Bs, Cs, Os;
};
struct TArgs {
    GD gd[5];
    int K, csr, csc, hasC, hasD, hasO, hasOT, sym;
    float alpha, beta;
};

__device__ __forceinline__ void ldplane(uint32_t smbase, const bf* g,
                                        int r0, int Kd, int kt, int tid) {
#pragma unroll
    for (int i = 0; i < 2; i++) {
        int idx = tid + i * 256;
        int row = idx >> 2;
        int ch = (idx & 3) << 3;
        const bf* src = g + (long)(r0 + row) * Kd + kt + ch;
        cp16(smbase + (uint32_t)(row * AST + ch) * 2u, src);
    }
}

__global__ __launch_bounds__(256, 1) void tgemm(const __grid_constant__ TArgs g) {
    extern __shared__ bf smh[];
    uint32_t smb = smem_u32(smh);

    const int tid = threadIdx.x;
    const int lane = tid & 31;
    const int wid = tid >> 5;
    const int wm = wid >> 2;
    const int wn = wid & 3;
    const int z = blockIdx.z;
    const GD& d = g.gd[z >> 3];
    const long zb = z & 7;

    int row0, col0, bi = 0, bj = 0;
    if (g.sym) {
        int t = blockIdx.x;
        int i = 0;
        while (t >= (i + 1) * (i + 2) / 2) i++;
        bi = i; bj = t - i * (i + 1) / 2;
        row0 = bi * 128; col0 = bj * 128;
    } else {
        row0 = blockIdx.y * 128; col0 = blockIdx.x * 128;
    }

    const bf* Ah = d.Ah + zb * d.As;
    const bf* Al = d.Al + zb * d.As;
    const bf* Bh = d.Bh + zb * d.Bs;
    const bf* Bl = d.Bl + zb * d.Bs;
    const int Kd = g.K;
    const int nslab = Kd >> 5;

    float acc[4][4][4];
#pragma unroll
    for (int i = 0; i < 4; i++)
#pragma unroll
        for (int j = 0; j < 4; j++)
#pragma unroll
            for (int r = 0; r < 4; r++) acc[i][j][r] = 0.f;

    const int lrow = lane & 15;
    const int lcol = (lane >> 4) << 3;

    // prologue: stages 0,1
    {
        ldplane(smb,                   Ah, row0, Kd, 0, tid);
        ldplane(smb + PLANE_H * 2,     Al, row0, Kd, 0, tid);
        ldplane(smb + 2 * PLANE_H * 2, Bh, col0, Kd, 0, tid);
        ldplane(smb + 3 * PLANE_H * 2, Bl, col0, Kd, 0, tid);
        cp_commit();
        uint32_t sb = smb + STAGE_H * 2;
        ldplane(sb,                   Ah, row0, Kd, 32, tid);
        ldplane(sb + PLANE_H * 2,     Al, row0, Kd, 32, tid);
        ldplane(sb + 2 * PLANE_H * 2, Bh, col0, Kd, 32, tid);
        ldplane(sb + 3 * PLANE_H * 2, Bl, col0, Kd, 32, tid);
        cp_commit();
    }

    for (int s = 0; s < nslab; s++) {
        if (s < nslab - 1) cp_wait<1>(); else cp_wait<0>();
        __syncthreads();
        if (s + 2 < nslab) {
            uint32_t sb = smb + (uint32_t)(((s + 2) % NSTAGE) * STAGE_H) * 2u;
            int kt = (s + 2) << 5;
            ldplane(sb,                   Ah, row0, Kd, kt, tid);
            ldplane(sb + PLANE_H * 2,     Al, row0, Kd, kt, tid);
            ldplane(sb + 2 * PLANE_H * 2, Bh, col0, Kd, kt, tid);
            ldplane(sb + 3 * PLANE_H * 2, Bl, col0, Kd, kt, tid);
            cp_commit();
        }

        uint32_t sb = smb + (uint32_t)((s % NSTAGE) * STAGE_H) * 2u;
#pragma unroll
        for (int k16 = 0; k16 < 2; k16++) {
            const int kh = k16 * 16 + lcol;
            uint32_t ahf[4][4], alf[4][4], bhf[2][4], blf[2][4];
#pragma unroll
            for (int mt = 0; mt < 4; mt++) {
                int ar = wm * 64 + mt * 16 + lrow;
                uint32_t off = (uint32_t)(ar * AST + kh) * 2u;
                ldm4(ahf[mt], sb + off);
                ldm4(alf[mt], sb + PLANE_H * 2 + off);
            }
#pragma unroll
            for (int pr = 0; pr < 2; pr++) {
                int br = wn * 32 + pr * 16 + lrow;
                uint32_t off = (uint32_t)(br * AST + kh) * 2u;
                ldm4(bhf[pr], sb + 2 * PLANE_H * 2 + off);
                ldm4(blf[pr], sb + 3 * PLANE_H * 2 + off);
            }
#pragma unroll
            for (int mt = 0; mt < 4; mt++) {
#pragma unroll
                for (int nt = 0; nt < 4; nt++) {
                    int pr = nt >> 1, hi = nt & 1;
                    uint32_t bh2[2] = {bhf[pr][hi], bhf[pr][hi + 2]};
                    uint32_t bl2[2] = {blf[pr][hi], blf[pr][hi + 2]};
                    mma16816(acc[mt][nt], ahf[mt], bh2);
                    mma16816(acc[mt][nt], ahf[mt], bl2);
                    mma16816(acc[mt][nt], alf[mt], bh2);
                }
            }
        }
    }

    // epilogue
    if (g.hasOT) __syncthreads();
    float* tsb = (float*)smh;
    float* C = d.C + zb * d.Cs;
    const float* Dm = d.Dm + zb * d.Cs;
    bf* oh = d.OH + zb * d.Os;
    bf* ol = d.OL + zb * d.Os;
    const int gr = lane >> 2, gc = (lane & 3) * 2;
    const int domirror = g.sym && (bi != bj);
#pragma unroll
    for (int mt = 0; mt < 4; mt++) {
#pragma unroll
        for (int nt = 0; nt < 4; nt++) {
#pragma unroll
            for (int rg = 0; rg < 4; rg++) {
                int rl = wm * 64 + mt * 16 + gr + ((rg >> 1) << 3);
                int cl = wn * 32 + nt * 8 + gc + (rg & 1);
                int r = row0 + rl, c = col0 + cl;
                long off = (long)r * g.csr + (long)c * g.csc;
                float val = g.alpha * acc[mt][nt][rg];
                if (g.hasD) val += g.beta * Dm[off];
                if (g.hasC) C[off] = val;
                bf vh = __float2bfloat16(val);
                bf vl = __float2bfloat16(val - __bfloat162float(vh));
                if (g.hasO) { oh[off] = vh; ol[off] = vl; }
                if (domirror) {
                    long offm = (long)c * g.csr + (long)r * g.csc;
                    if (g.hasC) C[offm] = val;
                    if (g.hasO) { oh[offm] = vh; ol[offm] = vl; }
                }
                if (g.hasOT) tsb[rl * 129 + cl] = val;
            }
        }
    }
    if (g.hasOT) {
        __syncthreads();
        bf* oth = d.OTH + zb * d.Os;
        bf* otl = d.OTL + zb * d.Os;
#pragma unroll 4
        for (int i = 0; i < 64; i++) {
            int idx = tid + i * 256;
            int cl = idx >> 7;
            int rl = idx & 127;
            float v = tsb[rl * 129 + cl];
            long off = (long)(col0 + cl) * 512 + row0 + rl;
            bf h = __float2bfloat16(v);
            oth[off] = h;
            otl[off] = __float2bfloat16(v - __bfloat162float(h));
        }
    }
}

// ------------------------- transpose/split ---------------------------------
struct TSArgs {
    const float* src; long sbs; int srows, scols;
    bf *pH, *pL; long pbs;
    bf *tH, *tL; long tbs;
};
__global__ void k_tsplit(const __grid_constant__ TSArgs a) {
    __shared__ float tile[32][33];
    int z = blockIdx.z;
    const float* S = a.src + (long)z * a.sbs;
    int c0 = blockIdx.x * 32, r0 = blockIdx.y * 32;
    int tx = threadIdx.x, ty = threadIdx.y;
#pragma unroll
    for (int j = 0; j < 4; j++) {
        int r = r0 + ty + j * 8;
        float v = S[(long)r * a.scols + c0 + tx];
        tile[ty + j * 8][tx] = v;
        if (a.pH) {
            long o = (long)z * a.pbs + (long)r * a.scols + c0 + tx;
            wsplit(a.pH, a.pL, o, v);
        }
    }
    __syncthreads();
    if (a.tH) {
#pragma unroll
        for (int j = 0; j < 4; j++) {
            int c = c0 + ty + j * 8;
            float v = tile[tx][ty + j * 8];
            long o = (long)z * a.tbs + (long)c * a.srows + r0 + tx;
            wsplit(a.tH, a.tL, o, v);
        }
    }
}

// ------------------------- elementwise kernels ------------------------------
__global__ void k_init(const float* w0, const float* w1, const float* w2) {
    int row = blockIdx.x;
    int m = row >> 9, w = m >> 3, bh = m & 7, r = row & 511;
    const float* src = (w == 0 ? w0 : (w == 1 ? w1 : w2)) + (long)bh * MSZ + (long)r * 512;
    long mo = (long)m * MSZ + (long)r * 512;
    int t = threadIdx.x;
    float ss = 0.f;
#pragma unroll
    for (int j = 0; j < 4; j++) {
        int c = t + j * 128;
        float v = src[c];
        g_f[F_WM + mo + c] = v;
        g_f[F_WC + mo + c] = v;
        g_f[F_DM + mo + c] = 0.f;
        wsplit(g_h + H_WCH, g_h + H_WCL, mo + c, v);
        ss += v * v;
    }
    __shared__ float red[128];
    red[t] = ss; __syncthreads();
    for (int s = 64; s > 0; s >>= 1) { if (t < s) red[t] += red[t + s]; __syncthreads(); }
    if (t == 0) g_f[F_WNORM + (long)m * 512 + r] = sqrtf(red[0]);
}

__global__ void k_splitKQ(const float* kin, const float* q, int cbase) {
    long idx = blockIdx.x * 256L + threadIdx.x;
    int d = idx & 511;
    int t = (int)((idx >> 9) & 255);
    int bh = (int)(idx >> 17);
    long so = (long)bh * TDSl + (long)(cbase + t) * DD + d;
    wsplit(g_h + H_KH, g_h + H_KL, idx, kin[so]);
    wsplit(g_h + H_QH, g_h + H_QL, idx, q[so]);
}

__global__ void k_ew12(const float* kin, const float* lr0, const float* lr1,
                       const float* lr2, int cbase) {
    long idx = blockIdx.x * 256L + threadIdx.x;
    {
        int t = idx & (CS - 1);
        int bh = (int)(idx >> 17);
        float gba = g_f[F_GBA + idx], hbm = g_f[F_HBM + idx], dh = g_f[F_DHID + idx];
        float sg = sigf(gba), sil = gba * sg;
        float hidden = sil * hbm;
        float l1 = lr1[(long)bh * TT + cbase + t];
        wsplit(g_h + H_HLH, g_h + H_HLL, idx, hidden * l1);
        wsplit(g_h + H_DBH, g_h + H_DBL, idx, dh * sil);
        float dgate = dh * hbm;
        wsplit(g_h + H_DGH, g_h + H_DGL, idx, dgate * sg * (1.f + gba * (1.f - sg)));
        float g0v = g_f[F_G0 + idx], hv = g_f[F_HH + idx];
        g_f[F_GH + idx] = g0v * sigf(g0v) * hv;
    }
    {
        int d = idx & 511;
        int t = (int)((idx >> 9) & 255);
        int bh = (int)(idx >> 17);
        float kv = kin[(long)bh * TDSl + (long)(cbase + t) * DD + d];
        g_f[F_KL0 + idx] = kv * lr0[(long)bh * TT + cbase + t];
        g_f[F_KL2 + idx] = kv * lr2[(long)bh * TT + cbase + t];
    }
}

__global__ void k_ewfwd() {
    long idx = blockIdx.x * 256L + threadIdx.x;
    float g0v = g_f[F_G0 + idx], hv = g_f[F_HH + idx];
    g_f[F_GH + idx] = g0v * sigf(g0v) * hv;
}

__global__ void k_scalars(const float* mom, const float* mlt, int cbase) {
    int bh = blockIdx.x;
    int t = threadIdx.x;
    __shared__ float r1[256], r2[256];
    r1[t] = mom[(long)bh * TT + cbase + t];
    r2[t] = mlt[(long)bh * TT + cbase + t];
    __syncthreads();
    for (int s = 128; s > 0; s >>= 1) {
        if (t < s) { r1[t] += r1[t + s]; r2[t] += r2[t + s]; }
        __syncthreads();
    }
    if (t == 0) { g_f[F_MI + bh] = r1[0] * (1.f / CS); g_f[F_MLI + bh] = r2[0] * (1.f / CS); }
}

__global__ void k_dwupd() {
    long idx = blockIdx.x * 256L + threadIdx.x;
    int m = (int)(idx >> 18);
    int bh = m & 7;
    g_f[F_DM + idx] = g_f[F_DW + idx] + g_f[F_DM + idx] * g_f[F_MI + bh];
}

__global__ void k_norm24() {
    int m = blockIdx.x;
    int t = threadIdx.x;
    const float* p = g_f + F_DM + (long)m * MSZ;
    float s = 0.f;
    for (int i = t; i < MSZ; i += 256) { float v = p[i]; s += v * v; }
    __shared__ float red[256];
    red[t] = s; __syncthreads();
    for (int st = 128; st > 0; st >>= 1) { if (t < st) red[t] += red[t + st]; __syncthreads(); }
    if (t == 0) g_f[F_RNS + m] = 1.f / (sqrtf(red[0]) + 1e-7f);
}

__global__ void k_xscale() {
    long idx = blockIdx.x * 256L + threadIdx.x;
    int m = (int)(idx >> 18);
    float v = g_f[F_DM + idx] * g_f[F_RNS + m];
    g_f[F_X0 + idx] = v;
    wsplit(g_h + H_XH, g_h + H_XL, idx, v);
}

__global__ void k_wupd(const float* x) {
    int row = blockIdx.x;
    int m = row >> 9, bh = m & 7, r = row & 511;
    long mo = (long)m * MSZ + (long)r * 512;
    const float* xp = x + mo;
    float ml = g_f[F_MLI + bh];
    int t = threadIdx.x;
    float vals[4];
    float ss = 0.f;
#pragma unroll
    for (int j = 0; j < 4; j++) {
        int c = t + j * 128;
        float v = g_f[F_WM + mo + c] + xp[c] * ml;
        g_f[F_WM + mo + c] = v;
        vals[j] = v;
        ss += v * v;
    }
    __shared__ float red[128];
    red[t] = ss; __syncthreads();
    for (int s = 64; s > 0; s >>= 1) { if (t < s) red[t] += red[t + s]; __syncthreads(); }
    float scale = g_f[F_WNORM + (long)m * 512 + r] / (sqrtf(red[0]) + 1e-5f);
#pragma unroll
    for (int j = 0; j < 4; j++) {
        int c = t + j * 128;
        float w = vals[j] * scale;
        g_f[F_WC + mo + c] = w;
        wsplit(g_h + H_WCH, g_h + H_WCL, mo + c, w);
    }
}

// ------------------------- host orchestration -------------------------------
static void setgd(GD& d, const bf* Ah, const bf* Al, long As,
                  const bf* Bh, const bf* Bl, long Bs,
                  float* C, const float* Dm, long Cs,
                  bf* OH, bf* OL, bf* OTH, bf* OTL, long Os) {
    d.Ah = Ah; d.Al = Al; d.Bh = Bh; d.Bl = Bl;
    d.C = C; d.Dm = Dm; d.OH = OH; d.OL = OL; d.OTH = OTH; d.OTL = OTL;
    d.As = As; d.Bs = Bs; d.Cs = Cs; d.Os = Os;
}
static void setflags(TArgs& g, int K, int csr, int csc, int hasC, int hasD, int hasO,
                     int hasOT, int sym, float alpha, float beta) {
    g.K = K; g.csr = csr; g.csc = csc; g.hasC = hasC; g.hasD = hasD;
    g.hasO = hasO; g.hasOT = hasOT; g.sym = sym; g.alpha = alpha; g.beta = beta;
}

static void ts(const float* src, long sbs, int srows, int scols,
               bf* pH, bf* pL, long pbs, bf* tH, bf* tL, long tbs, int batch) {
    TSArgs a;
    a.src = src; a.sbs = sbs; a.srows = srows; a.scols = scols;
    a.pH = pH; a.pL = pL; a.pbs = pbs;
    a.tH = tH; a.tL = tL; a.tbs = tbs;
    k_tsplit<<<dim3(scols / 32, srows / 32, batch), dim3(32, 8)>>>(a);
}

static const float NSC[5][3] = {
    {4.0848f, -6.8946f, 2.927f},
    {3.9505f, -6.3029f, 2.6377f},
    {3.7418f, -5.5913f, 2.3037f},
    {2.8769f, -3.1427f, 1.2046f},
    {2.8366f, -3.0525f, 1.2012f}};

extern "C" void kernel_launch(void* const* d_in, const int* in_sizes, int n_in,
                              void* d_out, int out_size) {
    const float* w0  = (const float*)d_in[0];
    const float* w1  = (const float*)d_in[1];
    const float* w2  = (const float*)d_in[2];
    const float* q   = (const float*)d_in[3];
    const float* kin = (const float*)d_in[4];
    const float* v   = (const float*)d_in[5];
    const float* lr0 = (const float*)d_in[6];
    const float* lr1 = (const float*)d_in[7];
    const float* lr2 = (const float*)d_in[8];
    const float* mom = (const float*)d_in[9];
    const float* mlt = (const float*)d_in[10];
    float* out = (float*)d_out;

    static int smset = 0;
    if (!smset) {
        cudaFuncSetAttribute(tgemm, cudaFuncAttributeMaxDynamicSharedMemorySize, SMEM_TOTAL);
        smset = 1;
    }

    float* F;
    bf* H;
    cudaGetSymbolAddress((void**)&F, g_f);
    cudaGetSymbolAddress((void**)&H, g_h);

    k_init<<<NMAT * 512, 128>>>(w0, w1, w2);
    ts(F + F_WC + 8L * MSZ, MSZ, 512, 512, 0, 0, 0, H + H_W1TH, H + H_W1TL, MSZ, 8);

    for (int ci = 0; ci < NCHUNK; ci++) {
        int cb = ci * CS;

        k_splitKQ<<<(int)(CHT / 256), 256>>>(kin, q, cb);
        ts(v + (long)cb * DD, TDSl, 256, 512,
           H + H_VH, H + H_VL, CHB, H + H_VTH, H + H_VTL, CHB, 8);

        // activation GEMMs: 5 groups of 8 -> one launch
        {
            TArgs g;
            setgd(g.gd[0], H + H_WCH, H + H_WCL, MSZ, H + H_KH, H + H_KL, CHB,
                  F + F_GBA, 0, CHB, 0, 0, 0, 0, 0);
            setgd(g.gd[1], H + H_WCH + 16L * MSZ, H + H_WCL + 16L * MSZ, MSZ,
                  H + H_KH, H + H_KL, CHB, F + F_HBM, 0, CHB, 0, 0, 0, 0, 0);
            setgd(g.gd[2], H + H_WCH + 16L * MSZ, H + H_WCL + 16L * MSZ, MSZ,
                  H + H_QH, H + H_QL, CHB, F + F_HH, 0, CHB, 0, 0, 0, 0, 0);
            setgd(g.gd[3], H + H_WCH, H + H_WCL, MSZ, H + H_QH, H + H_QL, CHB,
                  F + F_G0, 0, CHB, 0, 0, 0, 0, 0);
            setgd(g.gd[4], H + H_W1TH, H + H_W1TL, MSZ, H + H_VH, H + H_VL, CHB,
                  F + F_DHID, 0, CHB, 0, 0, 0, 0, 0);
            setflags(g, 512, CS, 1, 1, 0, 0, 0, 0, 1.f, 0.f);
            tgemm<<<dim3(2, 4, 40), 256, SMEM_TOTAL>>>(g);
        }

        k_ew12<<<(int)(CHT / 256), 256>>>(kin, lr0, lr1, lr2, cb);

        ts(F + F_GH, CHB, 512, 256, 0, 0, 0, H + H_GTH, H + H_GTL, CHB, 8);
        ts(F + F_KL0, CHB, 256, 512, 0, 0, 0, H + H_K0H, H + H_K0L, CHB, 8);
        ts(F + F_KL2, CHB, 256, 512, 0, 0, 0, H + H_K2H, H + H_K2L, CHB, 8);

        // chunk_out = w1c @ (gate*h)
        {
            TArgs g;
            setgd(g.gd[0], H + H_WCH + 8L * MSZ, H + H_WCL + 8L * MSZ, MSZ,
                  H + H_GTH, H + H_GTL, CHB,
                  out + (long)cb * DD, 0, TDSl, 0, 0, 0, 0, 0);
            setflags(g, 512, 1, DD, 1, 0, 0, 0, 0, 1.f, 0.f);
            tgemm<<<dim3(2, 4, 8), 256, SMEM_TOTAL>>>(g);
        }

        // dw GEMMs: 3 groups of 8 -> one launch
        {
            TArgs g;
            setgd(g.gd[0], H + H_DGH, H + H_DGL, CHB, H + H_K0H, H + H_K0L, CHB,
                  F + F_DW, 0, MSZ, 0, 0, 0, 0, 0);
            setgd(g.gd[1], H + H_VTH, H + H_VTL, CHB, H + H_HLH, H + H_HLL, CHB,
                  F + F_DW + 8L * MSZ, 0, MSZ, 0, 0, 0, 0, 0);
            setgd(g.gd[2], H + H_DBH, H + H_DBL, CHB, H + H_K2H, H + H_K2L, CHB,
                  F + F_DW + 16L * MSZ, 0, MSZ, 0, 0, 0, 0, 0);
            setflags(g, 256, 512, 1, 1, 0, 0, 0, 0, 1.f, 0.f);
            tgemm<<<dim3(4, 4, 24), 256, SMEM_TOTAL>>>(g);
        }

        k_scalars<<<BH, 256>>>(mom, mlt, cb);
        k_dwupd<<<(int)(NM_ / 256), 256>>>();
        k_norm24<<<NMAT, 256>>>();
        k_xscale<<<(int)(NM_ / 256), 256>>>();
        ts(F + F_X0, MSZ, 512, 512, 0, 0, 0, H + H_XTH, H + H_XTL, MSZ, 24);

        // Newton-Schulz (5 iters, 24 matrices); XT planes ping-pong per iter
        float* Xc = F + F_X0;
        float* Xn = F + F_X1;
        for (int it = 0; it < 5; it++) {
            float aa = NSC[it][0], bb = NSC[it][1], cc = NSC[it][2];
            long xtA_h = (it & 1) ? H_XT2H : H_XTH;
            long xtA_l = (it & 1) ? H_XT2L : H_XTL;
            long xtB_h = (it & 1) ? H_XTH : H_XT2H;
            long xtB_l = (it & 1) ? H_XTL : H_XT2L;
            // A = X @ X^T : symmetric triangle
            {
                TArgs g;
                for (int j = 0; j < 3; j++) {
                    long mb = (long)j * 8 * MSZ;
                    setgd(g.gd[j], H + H_XH + mb, H + H_XL + mb, MSZ,
                          H + H_XH + mb, H + H_XL + mb, MSZ,
                          F + F_AB + mb, 0, MSZ,
                          H + H_AH + mb, H + H_AL + mb, 0, 0, MSZ);
                }
                setflags(g, 512, 512, 1, 1, 0, 1, 0, 1, 1.f, 0.f);
                tgemm<<<dim3(10, 1, 24), 256, SMEM_TOTAL>>>(g);
            }
            // B = b*A + c*(A@A) : symmetric triangle, bf16 planes only
            {
                TArgs g;
                for (int j = 0; j < 3; j++) {
                    long mb = (long)j * 8 * MSZ;
                    setgd(g.gd[j], H + H_AH + mb, H + H_AL + mb, MSZ,
                          H + H_AH + mb, H + H_AL + mb, MSZ,
                          0, F + F_AB + mb, MSZ,
                          H + H_BH + mb, H + H_BL + mb, 0, 0, MSZ);
                }
                setflags(g, 512, 512, 1, 0, 1, 1, 0, 1, cc, bb);
                tgemm<<<dim3(10, 1, 24), 256, SMEM_TOTAL>>>(g);
            }
            // X' = a*X + B@X : reads XT[it&1], epilogue writes XT[(it+1)&1]
            {
                TArgs g;
                for (int j = 0; j < 3; j++) {
                    long mb = (long)j * 8 * MSZ;
                    setgd(g.gd[j], H + H_BH + mb, H + H_BL + mb, MSZ,
                          H + xtA_h + mb, H + xtA_l + mb, MSZ,
                          Xn + mb, Xc + mb, MSZ,
                          H + H_XH + mb, H + H_XL + mb,
                          H + xtB_h + mb, H + xtB_l + mb, MSZ);
                }
                setflags(g, 512, 512, 1, 1, 1, 1, 1, 0, 1.f, aa);
                tgemm<<<dim3(4, 4, 24), 256, SMEM_TOTAL>>>(g);
            }
            float* tmp = Xc; Xc = Xn; Xn = tmp;
        }

        k_wupd<<<NMAT * 512, 128>>>(Xc);
        ts(F + F_WC + 8L * MSZ, MSZ, 512, 512, 0, 0, 0, H + H_W1TH, H + H_W1TL, MSZ, 8);
    }

    // final forward-only chunk
    {
        int cb = NCHUNK * CS;
        k_splitKQ<<<(int)(CHT / 256), 256>>>(kin, q, cb);
        {
            TArgs g;
            setgd(g.gd[0], H + H_WCH + 16L * MSZ, H + H_WCL + 16L * MSZ, MSZ,
                  H + H_QH, H + H_QL, CHB, F + F_HH, 0, CHB, 0, 0, 0, 0, 0);
            setgd(g.gd[1], H + H_WCH, H + H_WCL, MSZ, H + H_QH, H + H_QL, CHB,
                  F + F_G0, 0, CHB, 0, 0, 0, 0, 0);
            setflags(g, 512, CS, 1, 1, 0, 0, 0, 0, 1.f, 0.f);
            tgemm<<<dim3(2, 4, 16), 256, SMEM_TOTAL>>>(g);
        }
        k_ewfwd<<<(int)(CHT / 256), 256>>>();
        ts(F + F_GH, CHB, 512, 256, 0, 0, 0, H + H_GTH, H + H_GTL, CHB, 8);
        {
            TArgs g;
            setgd(g.gd[0], H + H_WCH + 8L * MSZ, H + H_WCL + 8L * MSZ, MSZ,
                  H + H_GTH, H + H_GTL, CHB,
                  out + (long)cb * DD, 0, TDSl, 0, 0, 0, 0, 0);
            setflags(g, 512, 1, DD, 1, 0, 0, 0, 0, 1.f, 0.f);
            tgemm<<<dim3(2, 4, 8), 256, SMEM_TOTAL>>>(g);
        }
    }
}

// round 9
// speedup vs baseline: 2.4906x; 1.1798x over previous
#include <cuda_runtime.h>
#include <cuda_bf16.h>
#include <math.h>
#include <stdint.h>

// ---------------------------------------------------------------------------
// LaCT SWIGLU fast-weight attention — mma.sync bf16-split-3 GEMM engine v2.3.
// v2.2 + occupancy-2 GEMM: 2-stage cp.async pipeline (80KB smem/CTA),
// __launch_bounds__(256,2), register-dieted inner loop (B-frags per k16,
// A-frags per mt) so two CTAs co-reside per SM and hide HMMA/ldmatrix latency.
// ---------------------------------------------------------------------------

#define BH 8
#define TT 4096
#define DD 512
#define DI 512
#define CS 256
#define NCHUNK 15
#define NMAT 24
#define MSZ (512 * 512)
#define AST 40
#define PLANE_H (128 * AST)
#define STAGE_H (4 * PLANE_H)
#define NSTAGE 2
#define SMEM_TOTAL (NSTAGE * STAGE_H * 2)  // 81920 bytes

static constexpr long NM_  = (long)NMAT * MSZ;
static constexpr long W1M_ = 8L * MSZ;
static constexpr long CHB  = (long)CS * DD;
static constexpr long CHT  = (long)BH * CHB;
static constexpr long TDSl = (long)TT * DD;

// fp32 heap
static constexpr long F_WM = 0, F_WC = NM_, F_DM = 2 * NM_, F_DW = 3 * NM_,
                      F_X0 = 4 * NM_, F_X1 = 5 * NM_, F_AB = 6 * NM_;
static constexpr long F_GBA = 7 * NM_, F_HBM = F_GBA + CHT, F_HH = F_HBM + CHT,
                      F_G0 = F_HH + CHT, F_DHID = F_G0 + CHT, F_GH = F_DHID + CHT,
                      F_KL0 = F_GH + CHT, F_KL2 = F_KL0 + CHT;
static constexpr long F_WNORM = F_KL2 + CHT, F_MI = F_WNORM + NMAT * 512L,
                      F_MLI = F_MI + 8, F_RNS = F_MLI + 8, F_TOT = F_RNS + NMAT;
__device__ __align__(256) float g_f[F_TOT];

// bf16 heap
static constexpr long H_WCH = 0, H_WCL = NM_,
                      H_W1TH = 2 * NM_, H_W1TL = H_W1TH + W1M_,
                      H_XH = H_W1TL + W1M_, H_XL = H_XH + NM_,
                      H_XTH = H_XL + NM_, H_XTL = H_XTH + NM_,
                      H_XT2H = H_XTL + NM_, H_XT2L = H_XT2H + NM_,
                      H_AH = H_XT2L + NM_, H_AL = H_AH + NM_,
                      H_BH = H_AL + NM_, H_BL = H_BH + NM_;
static constexpr long H_KH = H_BL + NM_, H_KL = H_KH + CHT, H_QH = H_KL + CHT,
                      H_QL = H_QH + CHT, H_VH = H_QL + CHT, H_VL = H_VH + CHT,
                      H_VTH = H_VL + CHT, H_VTL = H_VTH + CHT,
                      H_K0H = H_VTL + CHT, H_K0L = H_K0H + CHT,
                      H_K2H = H_K0L + CHT, H_K2L = H_K2H + CHT,
                      H_GTH = H_K2L + CHT, H_GTL = H_GTH + CHT,
                      H_HLH = H_GTL + CHT, H_HLL = H_HLH + CHT,
                      H_DGH = H_HLL + CHT, H_DGL = H_DGH + CHT,
                      H_DBH = H_DGL + CHT, H_DBL = H_DBH + CHT,
                      H_TOT = H_DBL + CHT;
__device__ __align__(256) __nv_bfloat16 g_h[H_TOT];

typedef __nv_bfloat16 bf;

// ------------------------- helpers -----------------------------------------
__device__ __forceinline__ uint32_t smem_u32(const void* p) {
    uint32_t a;
    asm("{ .reg .u64 t; cvta.to.shared.u64 t, %1; cvt.u32.u64 %0, t; }" : "=r"(a) : "l"(p));
    return a;
}
__device__ __forceinline__ void cp16(uint32_t dst, const void* src) {
    asm volatile("cp.async.cg.shared.global [%0], [%1], 16;" :: "r"(dst), "l"(src));
}
__device__ __forceinline__ void cp_commit() {
    asm volatile("cp.async.commit_group;" ::: "memory");
}
template <int N>
__device__ __forceinline__ void cp_wait() {
    asm volatile("cp.async.wait_group %0;" :: "n"(N) : "memory");
}
__device__ __forceinline__ void ldm4(uint32_t* f, uint32_t addr) {
    asm volatile("ldmatrix.sync.aligned.m8n8.x4.shared.b16 {%0,%1,%2,%3}, [%4];"
                 : "=r"(f[0]), "=r"(f[1]), "=r"(f[2]), "=r"(f[3]) : "r"(addr));
}
__device__ __forceinline__ void mma16816(float* c, const uint32_t* a, const uint32_t* b) {
    asm volatile("mma.sync.aligned.m16n8k16.row.col.f32.bf16.bf16.f32 "
                 "{%0,%1,%2,%3}, {%4,%5,%6,%7}, {%8,%9}, {%0,%1,%2,%3};"
                 : "+f"(c[0]), "+f"(c[1]), "+f"(c[2]), "+f"(c[3])
                 : "r"(a[0]), "r"(a[1]), "r"(a[2]), "r"(a[3]), "r"(b[0]), "r"(b[1]));
}
__device__ __forceinline__ void wsplit(bf* H, bf* L, long i, float v) {
    bf h = __float2bfloat16(v);
    H[i] = h;
    L[i] = __float2bfloat16(v - __bfloat162float(h));
}
__device__ __forceinline__ float sigf(float x) { return 1.f / (1.f + expf(-x)); }

// ------------------------- GEMM kernel --------------------------------------
struct GD {
    const bf *Ah, *Al, *Bh, *Bl;
    float* C;
    const float* Dm;
    bf *OH, *OL, *OTH, *OTL;
    long As, Bs, Cs, Os;
};
struct TArgs {
    GD gd[5];
    int K, csr, csc, hasC, hasD, hasO, hasOT, sym;
    float alpha, beta;
};

__device__ __forceinline__ void ldplane(uint32_t smbase, const bf* g,
                                        int r0, int Kd, int kt, int tid) {
#pragma unroll
    for (int i = 0; i < 2; i++) {
        int idx = tid + i * 256;
        int row = idx >> 2;
        int ch = (idx & 3) << 3;
        const bf* src = g + (long)(r0 + row) * Kd + kt + ch;
        cp16(smbase + (uint32_t)(row * AST + ch) * 2u, src);
    }
}

__global__ __launch_bounds__(256, 2) void tgemm(const __grid_constant__ TArgs g) {
    extern __shared__ bf smh[];
    uint32_t smb = smem_u32(smh);

    const int tid = threadIdx.x;
    const int lane = tid & 31;
    const int wid = tid >> 5;
    const int wm = wid >> 2;
    const int wn = wid & 3;
    const int z = blockIdx.z;
    const GD& d = g.gd[z >> 3];
    const long zb = z & 7;

    int row0, col0, bi = 0, bj = 0;
    if (g.sym) {
        int t = blockIdx.x;
        int i = 0;
        while (t >= (i + 1) * (i + 2) / 2) i++;
        bi = i; bj = t - i * (i + 1) / 2;
        row0 = bi * 128; col0 = bj * 128;
    } else {
        row0 = blockIdx.y * 128; col0 = blockIdx.x * 128;
    }

    const bf* Ah = d.Ah + zb * d.As;
    const bf* Al = d.Al + zb * d.As;
    const bf* Bh = d.Bh + zb * d.Bs;
    const bf* Bl = d.Bl + zb * d.Bs;
    const int Kd = g.K;
    const int nslab = Kd >> 5;

    float acc[4][4][4];
#pragma unroll
    for (int i = 0; i < 4; i++)
#pragma unroll
        for (int j = 0; j < 4; j++)
#pragma unroll
            for (int r = 0; r < 4; r++) acc[i][j][r] = 0.f;

    const int lrow = lane & 15;
    const int lcol = (lane >> 4) << 3;

    // prologue: stage 0
    {
        ldplane(smb,                   Ah, row0, Kd, 0, tid);
        ldplane(smb + PLANE_H * 2,     Al, row0, Kd, 0, tid);
        ldplane(smb + 2 * PLANE_H * 2, Bh, col0, Kd, 0, tid);
        ldplane(smb + 3 * PLANE_H * 2, Bl, col0, Kd, 0, tid);
        cp_commit();
    }

    for (int s = 0; s < nslab; s++) {
        if (s + 1 < nslab) {
            uint32_t sb = smb + (uint32_t)(((s + 1) & 1) * STAGE_H) * 2u;
            int kt = (s + 1) << 5;
            ldplane(sb,                   Ah, row0, Kd, kt, tid);
            ldplane(sb + PLANE_H * 2,     Al, row0, Kd, kt, tid);
            ldplane(sb + 2 * PLANE_H * 2, Bh, col0, Kd, kt, tid);
            ldplane(sb + 3 * PLANE_H * 2, Bl, col0, Kd, kt, tid);
            cp_commit();
            cp_wait<1>();
        } else {
            cp_wait<0>();
        }
        __syncthreads();

        uint32_t sb = smb + (uint32_t)((s & 1) * STAGE_H) * 2u;
#pragma unroll
        for (int k16 = 0; k16 < 2; k16++) {
            const int kh = k16 * 16 + lcol;
            uint32_t bhf[2][4], blf[2][4];
#pragma unroll
            for (int pr = 0; pr < 2; pr++) {
                int br = wn * 32 + pr * 16 + lrow;
                uint32_t off = (uint32_t)(br * AST + kh) * 2u;
                ldm4(bhf[pr], sb + 2 * PLANE_H * 2 + off);
                ldm4(blf[pr], sb + 3 * PLANE_H * 2 + off);
            }
#pragma unroll
            for (int mt = 0; mt < 4; mt++) {
                uint32_t ahf[4], alf[4];
                int ar = wm * 64 + mt * 16 + lrow;
                uint32_t off = (uint32_t)(ar * AST + kh) * 2u;
                ldm4(ahf, sb + off);
                ldm4(alf, sb + PLANE_H * 2 + off);
#pragma unroll
                for (int nt = 0; nt < 4; nt++) {
                    int pr = nt >> 1, hi = nt & 1;
                    uint32_t bh2[2] = {bhf[pr][hi], bhf[pr][hi + 2]};
                    uint32_t bl2[2] = {blf[pr][hi], blf[pr][hi + 2]};
                    mma16816(acc[mt][nt], ahf, bh2);
                    mma16816(acc[mt][nt], ahf, bl2);
                    mma16816(acc[mt][nt], alf, bh2);
                }
            }
        }
        __syncthreads();
    }

    // epilogue
    float* tsb = (float*)smh;
    float* C = d.C + zb * d.Cs;
    const float* Dm = d.Dm + zb * d.Cs;
    bf* oh = d.OH + zb * d.Os;
    bf* ol = d.OL + zb * d.Os;
    const int gr = lane >> 2, gc = (lane & 3) * 2;
    const int domirror = g.sym && (bi != bj);
#pragma unroll
    for (int mt = 0; mt < 4; mt++) {
#pragma unroll
        for (int nt = 0; nt < 4; nt++) {
#pragma unroll
            for (int rg = 0; rg < 4; rg++) {
                int rl = wm * 64 + mt * 16 + gr + ((rg >> 1) << 3);
                int cl = wn * 32 + nt * 8 + gc + (rg & 1);
                int r = row0 + rl, c = col0 + cl;
                long off = (long)r * g.csr + (long)c * g.csc;
                float val = g.alpha * acc[mt][nt][rg];
                if (g.hasD) val += g.beta * Dm[off];
                if (g.hasC) C[off] = val;
                bf vh = __float2bfloat16(val);
                bf vl = __float2bfloat16(val - __bfloat162float(vh));
                if (g.hasO) { oh[off] = vh; ol[off] = vl; }
                if (domirror) {
                    long offm = (long)c * g.csr + (long)r * g.csc;
                    if (g.hasC) C[offm] = val;
                    if (g.hasO) { oh[offm] = vh; ol[offm] = vl; }
                }
                if (g.hasOT) tsb[rl * 129 + cl] = val;
            }
        }
    }
    if (g.hasOT) {
        __syncthreads();
        bf* oth = d.OTH + zb * d.Os;
        bf* otl = d.OTL + zb * d.Os;
#pragma unroll 4
        for (int i = 0; i < 64; i++) {
            int idx = tid + i * 256;
            int cl = idx >> 7;
            int rl = idx & 127;
            float v = tsb[rl * 129 + cl];
            long off = (long)(col0 + cl) * 512 + row0 + rl;
            bf h = __float2bfloat16(v);
            oth[off] = h;
            otl[off] = __float2bfloat16(v - __bfloat162float(h));
        }
    }
}

// ------------------------- transpose/split ---------------------------------
struct TSArgs {
    const float* src; long sbs; int srows, scols;
    bf *pH, *pL; long pbs;
    bf *tH, *tL; long tbs;
};
__global__ void k_tsplit(const __grid_constant__ TSArgs a) {
    __shared__ float tile[32][33];
    int z = blockIdx.z;
    const float* S = a.src + (long)z * a.sbs;
    int c0 = blockIdx.x * 32, r0 = blockIdx.y * 32;
    int tx = threadIdx.x, ty = threadIdx.y;
#pragma unroll
    for (int j = 0; j < 4; j++) {
        int r = r0 + ty + j * 8;
        float v = S[(long)r * a.scols + c0 + tx];
        tile[ty + j * 8][tx] = v;
        if (a.pH) {
            long o = (long)z * a.pbs + (long)r * a.scols + c0 + tx;
            wsplit(a.pH, a.pL, o, v);
        }
    }
    __syncthreads();
    if (a.tH) {
#pragma unroll
        for (int j = 0; j < 4; j++) {
            int c = c0 + ty + j * 8;
            float v = tile[tx][ty + j * 8];
            long o = (long)z * a.tbs + (long)c * a.srows + r0 + tx;
            wsplit(a.tH, a.tL, o, v);
        }
    }
}

// ------------------------- elementwise kernels ------------------------------
__global__ void k_init(const float* w0, const float* w1, const float* w2) {
    int row = blockIdx.x;
    int m = row >> 9, w = m >> 3, bh = m & 7, r = row & 511;
    const float* src = (w == 0 ? w0 : (w == 1 ? w1 : w2)) + (long)bh * MSZ + (long)r * 512;
    long mo = (long)m * MSZ + (long)r * 512;
    int t = threadIdx.x;
    float ss = 0.f;
#pragma unroll
    for (int j = 0; j < 4; j++) {
        int c = t + j * 128;
        float v = src[c];
        g_f[F_WM + mo + c] = v;
        g_f[F_WC + mo + c] = v;
        g_f[F_DM + mo + c] = 0.f;
        wsplit(g_h + H_WCH, g_h + H_WCL, mo + c, v);
        ss += v * v;
    }
    __shared__ float red[128];
    red[t] = ss; __syncthreads();
    for (int s = 64; s > 0; s >>= 1) { if (t < s) red[t] += red[t + s]; __syncthreads(); }
    if (t == 0) g_f[F_WNORM + (long)m * 512 + r] = sqrtf(red[0]);
}

__global__ void k_splitKQ(const float* kin, const float* q, int cbase) {
    long idx = blockIdx.x * 256L + threadIdx.x;
    int d = idx & 511;
    int t = (int)((idx >> 9) & 255);
    int bh = (int)(idx >> 17);
    long so = (long)bh * TDSl + (long)(cbase + t) * DD + d;
    wsplit(g_h + H_KH, g_h + H_KL, idx, kin[so]);
    wsplit(g_h + H_QH, g_h + H_QL, idx, q[so]);
}

__global__ void k_ew12(const float* kin, const float* lr0, const float* lr1,
                       const float* lr2, int cbase) {
    long idx = blockIdx.x * 256L + threadIdx.x;
    {
        int t = idx & (CS - 1);
        int bh = (int)(idx >> 17);
        float gba = g_f[F_GBA + idx], hbm = g_f[F_HBM + idx], dh = g_f[F_DHID + idx];
        float sg = sigf(gba), sil = gba * sg;
        float hidden = sil * hbm;
        float l1 = lr1[(long)bh * TT + cbase + t];
        wsplit(g_h + H_HLH, g_h + H_HLL, idx, hidden * l1);
        wsplit(g_h + H_DBH, g_h + H_DBL, idx, dh * sil);
        float dgate = dh * hbm;
        wsplit(g_h + H_DGH, g_h + H_DGL, idx, dgate * sg * (1.f + gba * (1.f - sg)));
        float g0v = g_f[F_G0 + idx], hv = g_f[F_HH + idx];
        g_f[F_GH + idx] = g0v * sigf(g0v) * hv;
    }
    {
        int d = idx & 511;
        int t = (int)((idx >> 9) & 255);
        int bh = (int)(idx >> 17);
        float kv = kin[(long)bh * TDSl + (long)(cbase + t) * DD + d];
        g_f[F_KL0 + idx] = kv * lr0[(long)bh * TT + cbase + t];
        g_f[F_KL2 + idx] = kv * lr2[(long)bh * TT + cbase + t];
    }
}

__global__ void k_ewfwd() {
    long idx = blockIdx.x * 256L + threadIdx.x;
    float g0v = g_f[F_G0 + idx], hv = g_f[F_HH + idx];
    g_f[F_GH + idx] = g0v * sigf(g0v) * hv;
}

__global__ void k_scalars(const float* mom, const float* mlt, int cbase) {
    int bh = blockIdx.x;
    int t = threadIdx.x;
    __shared__ float r1[256], r2[256];
    r1[t] = mom[(long)bh * TT + cbase + t];
    r2[t] = mlt[(long)bh * TT + cbase + t];
    __syncthreads();
    for (int s = 128; s > 0; s >>= 1) {
        if (t < s) { r1[t] += r1[t + s]; r2[t] += r2[t + s]; }
        __syncthreads();
    }
    if (t == 0) { g_f[F_MI + bh] = r1[0] * (1.f / CS); g_f[F_MLI + bh] = r2[0] * (1.f / CS); }
}

__global__ void k_dwupd() {
    long idx = blockIdx.x * 256L + threadIdx.x;
    int m = (int)(idx >> 18);
    int bh = m & 7;
    g_f[F_DM + idx] = g_f[F_DW + idx] + g_f[F_DM + idx] * g_f[F_MI + bh];
}

__global__ void k_norm24() {
    int m = blockIdx.x;
    int t = threadIdx.x;
    const float* p = g_f + F_DM + (long)m * MSZ;
    float s = 0.f;
    for (int i = t; i < MSZ; i += 256) { float v = p[i]; s += v * v; }
    __shared__ float red[256];
    red[t] = s; __syncthreads();
    for (int st = 128; st > 0; st >>= 1) { if (t < st) red[t] += red[t + st]; __syncthreads(); }
    if (t == 0) g_f[F_RNS + m] = 1.f / (sqrtf(red[0]) + 1e-7f);
}

__global__ void k_xscale() {
    long idx = blockIdx.x * 256L + threadIdx.x;
    int m = (int)(idx >> 18);
    float v = g_f[F_DM + idx] * g_f[F_RNS + m];
    g_f[F_X0 + idx] = v;
    wsplit(g_h + H_XH, g_h + H_XL, idx, v);
}

__global__ void k_wupd(const float* x) {
    int row = blockIdx.x;
    int m = row >> 9, bh = m & 7, r = row & 511;
    long mo = (long)m * MSZ + (long)r * 512;
    const float* xp = x + mo;
    float ml = g_f[F_MLI + bh];
    int t = threadIdx.x;
    float vals[4];
    float ss = 0.f;
#pragma unroll
    for (int j = 0; j < 4; j++) {
        int c = t + j * 128;
        float v = g_f[F_WM + mo + c] + xp[c] * ml;
        g_f[F_WM + mo + c] = v;
        vals[j] = v;
        ss += v * v;
    }
    __shared__ float red[128];
    red[t] = ss; __syncthreads();
    for (int s = 64; s > 0; s >>= 1) { if (t < s) red[t] += red[t + s]; __syncthreads(); }
    float scale = g_f[F_WNORM + (long)m * 512 + r] / (sqrtf(red[0]) + 1e-5f);
#pragma unroll
    for (int j = 0; j < 4; j++) {
        int c = t + j * 128;
        float w = vals[j] * scale;
        g_f[F_WC + mo + c] = w;
        wsplit(g_h + H_WCH, g_h + H_WCL, mo + c, w);
    }
}

// ------------------------- host orchestration -------------------------------
static void setgd(GD& d, const bf* Ah, const bf* Al, long As,
                  const bf* Bh, const bf* Bl, long Bs,
                  float* C, const float* Dm, long Cs,
                  bf* OH, bf* OL, bf* OTH, bf* OTL, long Os) {
    d.Ah = Ah; d.Al = Al; d.Bh = Bh; d.Bl = Bl;
    d.C = C; d.Dm = Dm; d.OH = OH; d.OL = OL; d.OTH = OTH; d.OTL = OTL;
    d.As = As; d.Bs = Bs; d.Cs = Cs; d.Os = Os;
}
static void setflags(TArgs& g, int K, int csr, int csc, int hasC, int hasD, int hasO,
                     int hasOT, int sym, float alpha, float beta) {
    g.K = K; g.csr = csr; g.csc = csc; g.hasC = hasC; g.hasD = hasD;
    g.hasO = hasO; g.hasOT = hasOT; g.sym = sym; g.alpha = alpha; g.beta = beta;
}

static void ts(const float* src, long sbs, int srows, int scols,
               bf* pH, bf* pL, long pbs, bf* tH, bf* tL, long tbs, int batch) {
    TSArgs a;
    a.src = src; a.sbs = sbs; a.srows = srows; a.scols = scols;
    a.pH = pH; a.pL = pL; a.pbs = pbs;
    a.tH = tH; a.tL = tL; a.tbs = tbs;
    k_tsplit<<<dim3(scols / 32, srows / 32, batch), dim3(32, 8)>>>(a);
}

static const float NSC[5][3] = {
    {4.0848f, -6.8946f, 2.927f},
    {3.9505f, -6.3029f, 2.6377f},
    {3.7418f, -5.5913f, 2.3037f},
    {2.8769f, -3.1427f, 1.2046f},
    {2.8366f, -3.0525f, 1.2012f}};

extern "C" void kernel_launch(void* const* d_in, const int* in_sizes, int n_in,
                              void* d_out, int out_size) {
    const float* w0  = (const float*)d_in[0];
    const float* w1  = (const float*)d_in[1];
    const float* w2  = (const float*)d_in[2];
    const float* q   = (const float*)d_in[3];
    const float* kin = (const float*)d_in[4];
    const float* v   = (const float*)d_in[5];
    const float* lr0 = (const float*)d_in[6];
    const float* lr1 = (const float*)d_in[7];
    const float* lr2 = (const float*)d_in[8];
    const float* mom = (const float*)d_in[9];
    const float* mlt = (const float*)d_in[10];
    float* out = (float*)d_out;

    static int smset = 0;
    if (!smset) {
        cudaFuncSetAttribute(tgemm, cudaFuncAttributeMaxDynamicSharedMemorySize, SMEM_TOTAL);
        smset = 1;
    }

    float* F;
    bf* H;
    cudaGetSymbolAddress((void**)&F, g_f);
    cudaGetSymbolAddress((void**)&H, g_h);

    k_init<<<NMAT * 512, 128>>>(w0, w1, w2);
    ts(F + F_WC + 8L * MSZ, MSZ, 512, 512, 0, 0, 0, H + H_W1TH, H + H_W1TL, MSZ, 8);

    for (int ci = 0; ci < NCHUNK; ci++) {
        int cb = ci * CS;

        k_splitKQ<<<(int)(CHT / 256), 256>>>(kin, q, cb);
        ts(v + (long)cb * DD, TDSl, 256, 512,
           H + H_VH, H + H_VL, CHB, H + H_VTH, H + H_VTL, CHB, 8);

        // activation GEMMs: 5 groups of 8 -> one launch
        {
            TArgs g;
            setgd(g.gd[0], H + H_WCH, H + H_WCL, MSZ, H + H_KH, H + H_KL, CHB,
                  F + F_GBA, 0, CHB, 0, 0, 0, 0, 0);
            setgd(g.gd[1], H + H_WCH + 16L * MSZ, H + H_WCL + 16L * MSZ, MSZ,
                  H + H_KH, H + H_KL, CHB, F + F_HBM, 0, CHB, 0, 0, 0, 0, 0);
            setgd(g.gd[2], H + H_WCH + 16L * MSZ, H + H_WCL + 16L * MSZ, MSZ,
                  H + H_QH, H + H_QL, CHB, F + F_HH, 0, CHB, 0, 0, 0, 0, 0);
            setgd(g.gd[3], H + H_WCH, H + H_WCL, MSZ, H + H_QH, H + H_QL, CHB,
                  F + F_G0, 0, CHB, 0, 0, 0, 0, 0);
            setgd(g.gd[4], H + H_W1TH, H + H_W1TL, MSZ, H + H_VH, H + H_VL, CHB,
                  F + F_DHID, 0, CHB, 0, 0, 0, 0, 0);
            setflags(g, 512, CS, 1, 1, 0, 0, 0, 0, 1.f, 0.f);
            tgemm<<<dim3(2, 4, 40), 256, SMEM_TOTAL>>>(g);
        }

        k_ew12<<<(int)(CHT / 256), 256>>>(kin, lr0, lr1, lr2, cb);

        ts(F + F_GH, CHB, 512, 256, 0, 0, 0, H + H_GTH, H + H_GTL, CHB, 8);
        ts(F + F_KL0, CHB, 256, 512, 0, 0, 0, H + H_K0H, H + H_K0L, CHB, 8);
        ts(F + F_KL2, CHB, 256, 512, 0, 0, 0, H + H_K2H, H + H_K2L, CHB, 8);

        // chunk_out = w1c @ (gate*h)
        {
            TArgs g;
            setgd(g.gd[0], H + H_WCH + 8L * MSZ, H + H_WCL + 8L * MSZ, MSZ,
                  H + H_GTH, H + H_GTL, CHB,
                  out + (long)cb * DD, 0, TDSl, 0, 0, 0, 0, 0);
            setflags(g, 512, 1, DD, 1, 0, 0, 0, 0, 1.f, 0.f);
            tgemm<<<dim3(2, 4, 8), 256, SMEM_TOTAL>>>(g);
        }

        // dw GEMMs: 3 groups of 8 -> one launch
        {
            TArgs g;
            setgd(g.gd[0], H + H_DGH, H + H_DGL, CHB, H + H_K0H, H + H_K0L, CHB,
                  F + F_DW, 0, MSZ, 0, 0, 0, 0, 0);
            setgd(g.gd[1], H + H_VTH, H + H_VTL, CHB, H + H_HLH, H + H_HLL, CHB,
                  F + F_DW + 8L * MSZ, 0, MSZ, 0, 0, 0, 0, 0);
            setgd(g.gd[2], H + H_DBH, H + H_DBL, CHB, H + H_K2H, H + H_K2L, CHB,
                  F + F_DW + 16L * MSZ, 0, MSZ, 0, 0, 0, 0, 0);
            setflags(g, 256, 512, 1, 1, 0, 0, 0, 0, 1.f, 0.f);
            tgemm<<<dim3(4, 4, 24), 256, SMEM_TOTAL>>>(g);
        }

        k_scalars<<<BH, 256>>>(mom, mlt, cb);
        k_dwupd<<<(int)(NM_ / 256), 256>>>();
        k_norm24<<<NMAT, 256>>>();
        k_xscale<<<(int)(NM_ / 256), 256>>>();
        ts(F + F_X0, MSZ, 512, 512, 0, 0, 0, H + H_XTH, H + H_XTL, MSZ, 24);

        // Newton-Schulz (5 iters, 24 matrices); XT planes ping-pong per iter
        float* Xc = F + F_X0;
        float* Xn = F + F_X1;
        for (int it = 0; it < 5; it++) {
            float aa = NSC[it][0], bb = NSC[it][1], cc = NSC[it][2];
            long xtA_h = (it & 1) ? H_XT2H : H_XTH;
            long xtA_l = (it & 1) ? H_XT2L : H_XTL;
            long xtB_h = (it & 1) ? H_XTH : H_XT2H;
            long xtB_l = (it & 1) ? H_XTL : H_XT2L;
            // A = X @ X^T : symmetric triangle
            {
                TArgs g;
                for (int j = 0; j < 3; j++) {
                    long mb = (long)j * 8 * MSZ;
                    setgd(g.gd[j], H + H_XH + mb, H + H_XL + mb, MSZ,
                          H + H_XH + mb, H + H_XL + mb, MSZ,
                          F + F_AB + mb, 0, MSZ,
                          H + H_AH + mb, H + H_AL + mb, 0, 0, MSZ);
                }
                setflags(g, 512, 512, 1, 1, 0, 1, 0, 1, 1.f, 0.f);
                tgemm<<<dim3(10, 1, 24), 256, SMEM_TOTAL>>>(g);
            }
            // B = b*A + c*(A@A) : symmetric triangle, bf16 planes only
            {
                TArgs g;
                for (int j = 0; j < 3; j++) {
                    long mb = (long)j * 8 * MSZ;
                    setgd(g.gd[j], H + H_AH + mb, H + H_AL + mb, MSZ,
                          H + H_AH + mb, H + H_AL + mb, MSZ,
                          0, F + F_AB + mb, MSZ,
                          H + H_BH + mb, H + H_BL + mb, 0, 0, MSZ);
                }
                setflags(g, 512, 512, 1, 0, 1, 1, 0, 1, cc, bb);
                tgemm<<<dim3(10, 1, 24), 256, SMEM_TOTAL>>>(g);
            }
            // X' = a*X + B@X : reads XT[it&1], epilogue writes XT[(it+1)&1]
            {
                TArgs g;
                for (int j = 0; j < 3; j++) {
                    long mb = (long)j * 8 * MSZ;
                    setgd(g.gd[j], H + H_BH + mb, H + H_BL + mb, MSZ,
                          H + xtA_h + mb, H + xtA_l + mb, MSZ,
                          Xn + mb, Xc + mb, MSZ,
                          H + H_XH + mb, H + H_XL + mb,
                          H + xtB_h + mb, H + xtB_l + mb, MSZ);
                }
                setflags(g, 512, 512, 1, 1, 1, 1, 1, 0, 1.f, aa);
                tgemm<<<dim3(4, 4, 24), 256, SMEM_TOTAL>>>(g);
            }
            float* tmp = Xc; Xc = Xn; Xn = tmp;
        }

        k_wupd<<<NMAT * 512, 128>>>(Xc);
        ts(F + F_WC + 8L * MSZ, MSZ, 512, 512, 0, 0, 0, H + H_W1TH, H + H_W1TL, MSZ, 8);
    }

    // final forward-only chunk
    {
        int cb = NCHUNK * CS;
        k_splitKQ<<<(int)(CHT / 256), 256>>>(kin, q, cb);
        {
            TArgs g;
            setgd(g.gd[0], H + H_WCH + 16L * MSZ, H + H_WCL + 16L * MSZ, MSZ,
                  H + H_QH, H + H_QL, CHB, F + F_HH, 0, CHB, 0, 0, 0, 0, 0);
            setgd(g.gd[1], H + H_WCH, H + H_WCL, MSZ, H + H_QH, H + H_QL, CHB,
                  F + F_G0, 0, CHB, 0, 0, 0, 0, 0);
            setflags(g, 512, CS, 1, 1, 0, 0, 0, 0, 1.f, 0.f);
            tgemm<<<dim3(2, 4, 16), 256, SMEM_TOTAL>>>(g);
        }
        k_ewfwd<<<(int)(CHT / 256), 256>>>();
        ts(F + F_GH, CHB, 512, 256, 0, 0, 0, H + H_GTH, H + H_GTL, CHB, 8);
        {
            TArgs g;
            setgd(g.gd[0], H + H_WCH + 8L * MSZ, H + H_WCL + 8L * MSZ, MSZ,
                  H + H_GTH, H + H_GTL, CHB,
                  out + (long)cb * DD, 0, TDSl, 0, 0, 0, 0, 0);
            setflags(g, 512, 1, DD, 1, 0, 0, 0, 0, 1.f, 0.f);
            tgemm<<<dim3(2, 4, 8), 256, SMEM_TOTAL>>>(g);
        }
    }
}

// round 11
// speedup vs baseline: 2.6365x; 1.0586x over previous
#include <cuda_runtime.h>
#include <cuda_bf16.h>
#include <math.h>
#include <stdint.h>

// ---------------------------------------------------------------------------
// LaCT SWIGLU fast-weight attention — mma.sync bf16-split-3 GEMM engine v3.1.
// v3 (per-group GEMM config, fused momentum+norm epilogue, fused tiled
// elementwise/transpose kernels) + FIX: restore hasC guard on the symmetric
// mirror C-store (R10 wrote through a null C in the NS B-GEMM).
// ---------------------------------------------------------------------------

#define BH 8
#define TT 4096
#define DD 512
#define DI 512
#define CS 256
#define NCHUNK 15
#define NMAT 24
#define MSZ (512 * 512)
#define AST 40
#define PLANE_H (128 * AST)
#define STAGE_H (4 * PLANE_H)
#define NSTAGE 2
#define SMEM_TOTAL (NSTAGE * STAGE_H * 2)  // 81920 bytes

static constexpr long NM_  = (long)NMAT * MSZ;
static constexpr long W1M_ = 8L * MSZ;
static constexpr long CHB  = (long)CS * DD;
static constexpr long CHT  = (long)BH * CHB;
static constexpr long TDSl = (long)TT * DD;

// fp32 heap
static constexpr long F_WM = 0, F_WC = NM_, F_DM = 2 * NM_,
                      F_X0 = 3 * NM_, F_X1 = 4 * NM_, F_AB = 5 * NM_;
static constexpr long F_GBA = 6 * NM_, F_HBM = F_GBA + CHT, F_HH = F_HBM + CHT,
                      F_G0 = F_HH + CHT, F_DHID = F_G0 + CHT;
static constexpr long F_WNORM = F_DHID + CHT, F_MI = F_WNORM + NMAT * 512L,
                      F_MLI = F_MI + 8, F_RNS = F_MLI + 8,
                      F_RSP = F_RNS + NMAT, F_TOT = F_RSP + 512;
__device__ __align__(256) float g_f[F_TOT];

// bf16 heap
static constexpr long H_WCH = 0, H_WCL = NM_,
                      H_W1TH = 2 * NM_, H_W1TL = H_W1TH + W1M_,
                      H_XH = H_W1TL + W1M_, H_XL = H_XH + NM_,
                      H_XTH = H_XL + NM_, H_XTL = H_XTH + NM_,
                      H_XT2H = H_XTL + NM_, H_XT2L = H_XT2H + NM_,
                      H_AH = H_XT2L + NM_, H_AL = H_AH + NM_,
                      H_BH = H_AL + NM_, H_BL = H_BH + NM_;
static constexpr long H_KH = H_BL + NM_, H_KL = H_KH + CHT, H_QH = H_KL + CHT,
                      H_QL = H_QH + CHT, H_VH = H_QL + CHT, H_VL = H_VH + CHT,
                      H_VTH = H_VL + CHT, H_VTL = H_VTH + CHT,
                      H_K0H = H_VTL + CHT, H_K0L = H_K0H + CHT,
                      H_K2H = H_K0L + CHT, H_K2L = H_K2H + CHT,
                      H_GTH = H_K2L + CHT, H_GTL = H_GTH + CHT,
                      H_HLH = H_GTL + CHT, H_HLL = H_HLH + CHT,
                      H_DGH = H_HLL + CHT, H_DGL = H_DGH + CHT,
                      H_DBH = H_DGL + CHT, H_DBL = H_DBH + CHT,
                      H_TOT = H_DBL + CHT;
__device__ __align__(256) __nv_bfloat16 g_h[H_TOT];

typedef __nv_bfloat16 bf;

// ------------------------- helpers -----------------------------------------
__device__ __forceinline__ uint32_t smem_u32(const void* p) {
    uint32_t a;
    asm("{ .reg .u64 t; cvta.to.shared.u64 t, %1; cvt.u32.u64 %0, t; }" : "=r"(a) : "l"(p));
    return a;
}
__device__ __forceinline__ void cp16(uint32_t dst, const void* src) {
    asm volatile("cp.async.cg.shared.global [%0], [%1], 16;" :: "r"(dst), "l"(src));
}
__device__ __forceinline__ void cp_commit() {
    asm volatile("cp.async.commit_group;" ::: "memory");
}
template <int N>
__device__ __forceinline__ void cp_wait() {
    asm volatile("cp.async.wait_group %0;" :: "n"(N) : "memory");
}
__device__ __forceinline__ void ldm4(uint32_t* f, uint32_t addr) {
    asm volatile("ldmatrix.sync.aligned.m8n8.x4.shared.b16 {%0,%1,%2,%3}, [%4];"
                 : "=r"(f[0]), "=r"(f[1]), "=r"(f[2]), "=r"(f[3]) : "r"(addr));
}
__device__ __forceinline__ void mma16816(float* c, const uint32_t* a, const uint32_t* b) {
    asm volatile("mma.sync.aligned.m16n8k16.row.col.f32.bf16.bf16.f32 "
                 "{%0,%1,%2,%3}, {%4,%5,%6,%7}, {%8,%9}, {%0,%1,%2,%3};"
                 : "+f"(c[0]), "+f"(c[1]), "+f"(c[2]), "+f"(c[3])
                 : "r"(a[0]), "r"(a[1]), "r"(a[2]), "r"(a[3]), "r"(b[0]), "r"(b[1]));
}
__device__ __forceinline__ void wsplit(bf* H, bf* L, long i, float v) {
    bf h = __float2bfloat16(v);
    H[i] = h;
    L[i] = __float2bfloat16(v - __bfloat162float(h));
}
__device__ __forceinline__ float sigf(float x) { return 1.f / (1.f + expf(-x)); }

// ------------------------- GEMM kernel --------------------------------------
// flags: 1=hasC, 2=hasD, 4=hasO, 8=hasOT, 16=sym, 32=redsq
struct GD {
    const bf *Ah, *Al, *Bh, *Bl;
    float* C;
    const float* Dm;
    bf *OH, *OL, *OTH, *OTL;
    const float* betap;          // per-sub beta override (indexed by zb)
    long As, Bs, Cs, Os;
    int M, N, K, csr, csc, flags;
    float alpha, beta;
};
struct TArgs {
    GD gd[5];
};

__device__ __forceinline__ void ldplane(uint32_t smbase, const bf* g,
                                        int r0, int Kd, int kt, int tid) {
#pragma unroll
    for (int i = 0; i < 2; i++) {
        int idx = tid + i * 256;
        int row = idx >> 2;
        int ch = (idx & 3) << 3;
        const bf* src = g + (long)(r0 + row) * Kd + kt + ch;
        cp16(smbase + (uint32_t)(row * AST + ch) * 2u, src);
    }
}

__global__ __launch_bounds__(256, 2) void tgemm(const __grid_constant__ TArgs g) {
    extern __shared__ bf smh[];
    uint32_t smb = smem_u32(smh);

    const int tid = threadIdx.x;
    const int lane = tid & 31;
    const int wid = tid >> 5;
    const int wm = wid >> 2;
    const int wn = wid & 3;
    const int z = blockIdx.z;
    const GD& d = g.gd[z >> 3];
    const long zb = z & 7;
    const int flags = d.flags;

    int row0, col0, bi = 0, bj = 0;
    if (flags & 16) {
        int t = blockIdx.x;
        int i = 0;
        while (t >= (i + 1) * (i + 2) / 2) i++;
        bi = i; bj = t - i * (i + 1) / 2;
        row0 = bi * 128; col0 = bj * 128;
    } else {
        row0 = blockIdx.y * 128; col0 = blockIdx.x * 128;
        if (row0 >= d.M || col0 >= d.N) return;
    }

    const bf* Ah = d.Ah + zb * d.As;
    const bf* Al = d.Al + zb * d.As;
    const bf* Bh = d.Bh + zb * d.Bs;
    const bf* Bl = d.Bl + zb * d.Bs;
    const int Kd = d.K;
    const int nslab = Kd >> 5;

    float acc[4][4][4];
#pragma unroll
    for (int i = 0; i < 4; i++)
#pragma unroll
        for (int j = 0; j < 4; j++)
#pragma unroll
            for (int r = 0; r < 4; r++) acc[i][j][r] = 0.f;

    const int lrow = lane & 15;
    const int lcol = (lane >> 4) << 3;

    // prologue: stage 0
    {
        ldplane(smb,                   Ah, row0, Kd, 0, tid);
        ldplane(smb + PLANE_H * 2,     Al, row0, Kd, 0, tid);
        ldplane(smb + 2 * PLANE_H * 2, Bh, col0, Kd, 0, tid);
        ldplane(smb + 3 * PLANE_H * 2, Bl, col0, Kd, 0, tid);
        cp_commit();
    }

    for (int s = 0; s < nslab; s++) {
        if (s + 1 < nslab) {
            uint32_t sb = smb + (uint32_t)(((s + 1) & 1) * STAGE_H) * 2u;
            int kt = (s + 1) << 5;
            ldplane(sb,                   Ah, row0, Kd, kt, tid);
            ldplane(sb + PLANE_H * 2,     Al, row0, Kd, kt, tid);
            ldplane(sb + 2 * PLANE_H * 2, Bh, col0, Kd, kt, tid);
            ldplane(sb + 3 * PLANE_H * 2, Bl, col0, Kd, kt, tid);
            cp_commit();
            cp_wait<1>();
        } else {
            cp_wait<0>();
        }
        __syncthreads();

        uint32_t sb = smb + (uint32_t)((s & 1) * STAGE_H) * 2u;
#pragma unroll
        for (int k16 = 0; k16 < 2; k16++) {
            const int kh = k16 * 16 + lcol;
            uint32_t bhf[2][4], blf[2][4];
#pragma unroll
            for (int pr = 0; pr < 2; pr++) {
                int br = wn * 32 + pr * 16 + lrow;
                uint32_t off = (uint32_t)(br * AST + kh) * 2u;
                ldm4(bhf[pr], sb + 2 * PLANE_H * 2 + off);
                ldm4(blf[pr], sb + 3 * PLANE_H * 2 + off);
            }
#pragma unroll
            for (int mt = 0; mt < 4; mt++) {
                uint32_t ahf[4], alf[4];
                int ar = wm * 64 + mt * 16 + lrow;
                uint32_t off = (uint32_t)(ar * AST + kh) * 2u;
                ldm4(ahf, sb + off);
                ldm4(alf, sb + PLANE_H * 2 + off);
#pragma unroll
                for (int nt = 0; nt < 4; nt++) {
                    int pr = nt >> 1, hi = nt & 1;
                    uint32_t bh2[2] = {bhf[pr][hi], bhf[pr][hi + 2]};
                    uint32_t bl2[2] = {blf[pr][hi], blf[pr][hi + 2]};
                    mma16816(acc[mt][nt], ahf, bh2);
                    mma16816(acc[mt][nt], ahf, bl2);
                    mma16816(acc[mt][nt], alf, bh2);
                }
            }
        }
        __syncthreads();
    }

    // epilogue
    float* tsb = (float*)smh;
    float* C = d.C + zb * d.Cs;
    const float* Dm = d.Dm + zb * d.Cs;
    bf* oh = d.OH + zb * d.Os;
    bf* ol = d.OL + zb * d.Os;
    const float bcoef = d.betap ? d.betap[zb] : d.beta;
    const int gr = lane >> 2, gc = (lane & 3) * 2;
    const int domirror = (flags & 16) && (bi != bj);
    float ssq = 0.f;
#pragma unroll
    for (int mt = 0; mt < 4; mt++) {
#pragma unroll
        for (int nt = 0; nt < 4; nt++) {
#pragma unroll
            for (int rg = 0; rg < 4; rg++) {
                int rl = wm * 64 + mt * 16 + gr + ((rg >> 1) << 3);
                int cl = wn * 32 + nt * 8 + gc + (rg & 1);
                int r = row0 + rl, c = col0 + cl;
                long off = (long)r * d.csr + (long)c * d.csc;
                float val = d.alpha * acc[mt][nt][rg];
                if (flags & 2) val += bcoef * Dm[off];
                if (flags & 1) C[off] = val;
                if (flags & 32) ssq += val * val;
                bf vh = __float2bfloat16(val);
                bf vl = __float2bfloat16(val - __bfloat162float(vh));
                if (flags & 4) { oh[off] = vh; ol[off] = vl; }
                if (domirror) {
                    long offm = (long)c * d.csr + (long)r * d.csc;
                    if (flags & 1) C[offm] = val;
                    if (flags & 4) { oh[offm] = vh; ol[offm] = vl; }
                }
                if (flags & 8) tsb[rl * 129 + cl] = val;
            }
        }
    }
    if (flags & 32) {
#pragma unroll
        for (int o = 16; o > 0; o >>= 1) ssq += __shfl_xor_sync(0xffffffffu, ssq, o);
        float* rs = (float*)smh;
        if (lane == 0) rs[wid] = ssq;
        __syncthreads();
        if (tid == 0) {
            float tot = 0.f;
#pragma unroll
            for (int w = 0; w < 8; w++) tot += rs[w];
            g_f[F_RSP + (long)z * 16 + blockIdx.y * 4 + blockIdx.x] = tot;
        }
    }
    if (flags & 8) {
        __syncthreads();
        bf* oth = d.OTH + zb * d.Os;
        bf* otl = d.OTL + zb * d.Os;
#pragma unroll 4
        for (int i = 0; i < 64; i++) {
            int idx = tid + i * 256;
            int cl = idx >> 7;
            int rl = idx & 127;
            float v = tsb[rl * 129 + cl];
            long off = (long)(col0 + cl) * 512 + row0 + rl;
            bf h = __float2bfloat16(v);
            oth[off] = h;
            otl[off] = __float2bfloat16(v - __bfloat162float(h));
        }
    }
}

// ------------------------- transpose/split (fp32 src -> planes) -------------
struct TSArgs {
    const float* src; long sbs; int srows, scols;
    bf *pH, *pL; long pbs;
    bf *tH, *tL; long tbs;
};
__global__ void k_tsplit(const __grid_constant__ TSArgs a) {
    __shared__ float tile[32][33];
    int z = blockIdx.z;
    const float* S = a.src + (long)z * a.sbs;
    int c0 = blockIdx.x * 32, r0 = blockIdx.y * 32;
    int tx = threadIdx.x, ty = threadIdx.y;
#pragma unroll
    for (int j = 0; j < 4; j++) {
        int r = r0 + ty + j * 8;
        float v = S[(long)r * a.scols + c0 + tx];
        tile[ty + j * 8][tx] = v;
        if (a.pH) {
            long o = (long)z * a.pbs + (long)r * a.scols + c0 + tx;
            wsplit(a.pH, a.pL, o, v);
        }
    }
    __syncthreads();
    if (a.tH) {
#pragma unroll
        for (int j = 0; j < 4; j++) {
            int c = c0 + ty + j * 8;
            float v = tile[tx][ty + j * 8];
            long o = (long)z * a.tbs + (long)c * a.srows + r0 + tx;
            wsplit(a.tH, a.tL, o, v);
        }
    }
}

// ------------------------- elementwise/fused kernels ------------------------
__global__ void k_init(const float* w0, const float* w1, const float* w2) {
    int row = blockIdx.x;
    int m = row >> 9, w = m >> 3, bh = m & 7, r = row & 511;
    const float* src = (w == 0 ? w0 : (w == 1 ? w1 : w2)) + (long)bh * MSZ + (long)r * 512;
    long mo = (long)m * MSZ + (long)r * 512;
    int t = threadIdx.x;
    float ss = 0.f;
#pragma unroll
    for (int j = 0; j < 4; j++) {
        int c = t + j * 128;
        float v = src[c];
        g_f[F_WM + mo + c] = v;
        g_f[F_WC + mo + c] = v;
        g_f[F_DM + mo + c] = 0.f;
        wsplit(g_h + H_WCH, g_h + H_WCL, mo + c, v);
        ss += v * v;
    }
    __shared__ float red[128];
    red[t] = ss; __syncthreads();
    for (int s = 64; s > 0; s >>= 1) { if (t < s) red[t] += red[t + s]; __syncthreads(); }
    if (t == 0) g_f[F_WNORM + (long)m * 512 + r] = sqrtf(red[0]);
}

__global__ void k_splitKQ(const float* kin, const float* q, int cbase) {
    long idx = blockIdx.x * 256L + threadIdx.x;
    int dd = idx & 511;
    int t = (int)((idx >> 9) & 255);
    int bh = (int)(idx >> 17);
    long so = (long)bh * TDSl + (long)(cbase + t) * DD + dd;
    wsplit(g_h + H_KH, g_h + H_KL, idx, kin[so]);
    wsplit(g_h + H_QH, g_h + H_QL, idx, q[so]);
}

// ew1 quantities + gate-hidden transpose (GT planes), tiled over (di, t)
__global__ void k_ew12T(const float* lr1, int cbase) {
    __shared__ float tile[32][33];
    int bh = blockIdx.z;
    int t0 = blockIdx.x * 32, di0 = blockIdx.y * 32;
    int tx = threadIdx.x, ty = threadIdx.y;
    float l1 = lr1[(long)bh * TT + cbase + t0 + tx];
#pragma unroll
    for (int j = 0; j < 4; j++) {
        long idx = (long)bh * CHB + (long)(di0 + ty + 8 * j) * CS + t0 + tx;
        float gba = g_f[F_GBA + idx], hbm = g_f[F_HBM + idx], dh = g_f[F_DHID + idx];
        float sg = sigf(gba), sil = gba * sg;
        wsplit(g_h + H_HLH, g_h + H_HLL, idx, sil * hbm * l1);
        wsplit(g_h + H_DBH, g_h + H_DBL, idx, dh * sil);
        float dgate = dh * hbm;
        wsplit(g_h + H_DGH, g_h + H_DGL, idx, dgate * sg * (1.f + gba * (1.f - sg)));
        float g0v = g_f[F_G0 + idx], hv = g_f[F_HH + idx];
        tile[ty + 8 * j][tx] = g0v * sigf(g0v) * hv;
    }
    __syncthreads();
#pragma unroll
    for (int j = 0; j < 4; j++) {
        long o = (long)bh * CHB + (long)(t0 + ty + 8 * j) * DI + di0 + tx;
        wsplit(g_h + H_GTH, g_h + H_GTL, o, tile[tx][ty + 8 * j]);
    }
}

// forward-only gate-hidden transpose (final chunk)
__global__ void k_ewfwdT(int cbase) {
    __shared__ float tile[32][33];
    int bh = blockIdx.z;
    int t0 = blockIdx.x * 32, di0 = blockIdx.y * 32;
    int tx = threadIdx.x, ty = threadIdx.y;
#pragma unroll
    for (int j = 0; j < 4; j++) {
        long idx = (long)bh * CHB + (long)(di0 + ty + 8 * j) * CS + t0 + tx;
        float g0v = g_f[F_G0 + idx], hv = g_f[F_HH + idx];
        tile[ty + 8 * j][tx] = g0v * sigf(g0v) * hv;
    }
    __syncthreads();
#pragma unroll
    for (int j = 0; j < 4; j++) {
        long o = (long)bh * CHB + (long)(t0 + ty + 8 * j) * DI + di0 + tx;
        wsplit(g_h + H_GTH, g_h + H_GTL, o, tile[tx][ty + 8 * j]);
    }
}

// k*lr -> transposed K0/K2 planes, tiled over (t, d)
__global__ void k_ekT(const float* kin, const float* lr0, const float* lr2, int cbase) {
    __shared__ float tile[32][33];
    int bh = blockIdx.z;
    int t0 = blockIdx.x * 32, d0 = blockIdx.y * 32;
    int tx = threadIdx.x, ty = threadIdx.y;
#pragma unroll
    for (int j = 0; j < 4; j++)
        tile[ty + 8 * j][tx] =
            kin[(long)bh * TDSl + (long)(cbase + t0 + ty + 8 * j) * DD + d0 + tx];
    __syncthreads();
    float l0 = lr0[(long)bh * TT + cbase + t0 + tx];
    float l2 = lr2[(long)bh * TT + cbase + t0 + tx];
#pragma unroll
    for (int j = 0; j < 4; j++) {
        long o = (long)bh * CHB + (long)(d0 + ty + 8 * j) * CS + t0 + tx;
        float kv = tile[tx][ty + 8 * j];
        wsplit(g_h + H_K0H, g_h + H_K0L, o, kv * l0);
        wsplit(g_h + H_K2H, g_h + H_K2L, o, kv * l2);
    }
}

__global__ void k_scalars(const float* mom, const float* mlt, int cbase) {
    int bh = blockIdx.x;
    int t = threadIdx.x;
    __shared__ float r1[256], r2[256];
    r1[t] = mom[(long)bh * TT + cbase + t];
    r2[t] = mlt[(long)bh * TT + cbase + t];
    __syncthreads();
    for (int s = 128; s > 0; s >>= 1) {
        if (t < s) { r1[t] += r1[t + s]; r2[t] += r2[t + s]; }
        __syncthreads();
    }
    if (t == 0) { g_f[F_MI + bh] = r1[0] * (1.f / CS); g_f[F_MLI + bh] = r2[0] * (1.f / CS); }
}

__global__ void k_normfin() {
    int m = threadIdx.x;  // 24
    float s = 0.f;
#pragma unroll
    for (int i = 0; i < 16; i++) s += g_f[F_RSP + (long)(m + 8) * 16 + i];
    g_f[F_RNS + m] = 1.f / (sqrtf(s) + 1e-7f);
}

// dm*rns -> X0 fp32 + X planes + XT planes, tiled
__global__ void k_xsplit() {
    __shared__ float tile[32][33];
    int m = blockIdx.z;
    int c0 = blockIdx.x * 32, r0 = blockIdx.y * 32;
    int tx = threadIdx.x, ty = threadIdx.y;
    float rn = g_f[F_RNS + m];
#pragma unroll
    for (int j = 0; j < 4; j++) {
        long i = (long)m * MSZ + (long)(r0 + ty + 8 * j) * 512 + c0 + tx;
        float v = g_f[F_DM + i] * rn;
        g_f[F_X0 + i] = v;
        wsplit(g_h + H_XH, g_h + H_XL, i, v);
        tile[ty + 8 * j][tx] = v;
    }
    __syncthreads();
#pragma unroll
    for (int j = 0; j < 4; j++) {
        long o = (long)m * MSZ + (long)(c0 + ty + 8 * j) * 512 + r0 + tx;
        wsplit(g_h + H_XTH, g_h + H_XTL, o, tile[tx][ty + 8 * j]);
    }
}

__global__ void k_wupd(const float* x) {
    int row = blockIdx.x;
    int m = row >> 9, bh = m & 7, r = row & 511;
    long mo = (long)m * MSZ + (long)r * 512;
    const float* xp = x + mo;
    float ml = g_f[F_MLI + bh];
    int t = threadIdx.x;
    float vals[4];
    float ss = 0.f;
#pragma unroll
    for (int j = 0; j < 4; j++) {
        int c = t + j * 128;
        float v = g_f[F_WM + mo + c] + xp[c] * ml;
        g_f[F_WM + mo + c] = v;
        vals[j] = v;
        ss += v * v;
    }
    __shared__ float red[128];
    red[t] = ss; __syncthreads();
    for (int s = 64; s > 0; s >>= 1) { if (t < s) red[t] += red[t + s]; __syncthreads(); }
    float scale = g_f[F_WNORM + (long)m * 512 + r] / (sqrtf(red[0]) + 1e-5f);
#pragma unroll
    for (int j = 0; j < 4; j++) {
        int c = t + j * 128;
        float w = vals[j] * scale;
        g_f[F_WC + mo + c] = w;
        wsplit(g_h + H_WCH, g_h + H_WCL, mo + c, w);
    }
}

// ------------------------- host orchestration -------------------------------
static void setgd(GD& d, const bf* Ah, const bf* Al, long As,
                  const bf* Bh, const bf* Bl, long Bs,
                  float* C, const float* Dm, long Cs,
                  bf* OH, bf* OL, bf* OTH, bf* OTL, long Os,
                  int M, int N, int K, int csr, int csc, int flags,
                  float alpha, float beta, const float* betap) {
    d.Ah = Ah; d.Al = Al; d.Bh = Bh; d.Bl = Bl;
    d.C = C; d.Dm = Dm; d.OH = OH; d.OL = OL; d.OTH = OTH; d.OTL = OTL;
    d.betap = betap;
    d.As = As; d.Bs = Bs; d.Cs = Cs; d.Os = Os;
    d.M = M; d.N = N; d.K = K; d.csr = csr; d.csc = csc; d.flags = flags;
    d.alpha = alpha; d.beta = beta;
}

static void ts(const float* src, long sbs, int srows, int scols,
               bf* pH, bf* pL, long pbs, bf* tH, bf* tL, long tbs, int batch) {
    TSArgs a;
    a.src = src; a.sbs = sbs; a.srows = srows; a.scols = scols;
    a.pH = pH; a.pL = pL; a.pbs = pbs;
    a.tH = tH; a.tL = tL; a.tbs = tbs;
    k_tsplit<<<dim3(scols / 32, srows / 32, batch), dim3(32, 8)>>>(a);
}

static const float NSC[5][3] = {
    {4.0848f, -6.8946f, 2.927f},
    {3.9505f, -6.3029f, 2.6377f},
    {3.7418f, -5.5913f, 2.3037f},
    {2.8769f, -3.1427f, 1.2046f},
    {2.8366f, -3.0525f, 1.2012f}};

extern "C" void kernel_launch(void* const* d_in, const int* in_sizes, int n_in,
                              void* d_out, int out_size) {
    const float* w0  = (const float*)d_in[0];
    const float* w1  = (const float*)d_in[1];
    const float* w2  = (const float*)d_in[2];
    const float* q   = (const float*)d_in[3];
    const float* kin = (const float*)d_in[4];
    const float* v   = (const float*)d_in[5];
    const float* lr0 = (const float*)d_in[6];
    const float* lr1 = (const float*)d_in[7];
    const float* lr2 = (const float*)d_in[8];
    const float* mom = (const float*)d_in[9];
    const float* mlt = (const float*)d_in[10];
    float* out = (float*)d_out;

    static int smset = 0;
    if (!smset) {
        cudaFuncSetAttribute(tgemm, cudaFuncAttributeMaxDynamicSharedMemorySize, SMEM_TOTAL);
        smset = 1;
    }

    float* F;
    bf* H;
    cudaGetSymbolAddress((void**)&F, g_f);
    cudaGetSymbolAddress((void**)&H, g_h);

    k_init<<<NMAT * 512, 128>>>(w0, w1, w2);
    ts(F + F_WC + 8L * MSZ, MSZ, 512, 512, 0, 0, 0, H + H_W1TH, H + H_W1TL, MSZ, 8);

    for (int ci = 0; ci < NCHUNK; ci++) {
        int cb = ci * CS;

        k_scalars<<<BH, 256>>>(mom, mlt, cb);
        k_splitKQ<<<(int)(CHT / 256), 256>>>(kin, q, cb);
        ts(v + (long)cb * DD, TDSl, 256, 512,
           H + H_VH, H + H_VL, CHB, H + H_VTH, H + H_VTL, CHB, 8);

        // activation GEMMs: 5 groups of 8 -> one launch
        {
            TArgs g;
            setgd(g.gd[0], H + H_WCH, H + H_WCL, MSZ, H + H_KH, H + H_KL, CHB,
                  F + F_GBA, 0, CHB, 0, 0, 0, 0, 0,
                  512, 256, 512, CS, 1, 1, 1.f, 0.f, 0);
            setgd(g.gd[1], H + H_WCH + 16L * MSZ, H + H_WCL + 16L * MSZ, MSZ,
                  H + H_KH, H + H_KL, CHB, F + F_HBM, 0, CHB, 0, 0, 0, 0, 0,
                  512, 256, 512, CS, 1, 1, 1.f, 0.f, 0);
            setgd(g.gd[2], H + H_WCH + 16L * MSZ, H + H_WCL + 16L * MSZ, MSZ,
                  H + H_QH, H + H_QL, CHB, F + F_HH, 0, CHB, 0, 0, 0, 0, 0,
                  512, 256, 512, CS, 1, 1, 1.f, 0.f, 0);
            setgd(g.gd[3], H + H_WCH, H + H_WCL, MSZ, H + H_QH, H + H_QL, CHB,
                  F + F_G0, 0, CHB, 0, 0, 0, 0, 0,
                  512, 256, 512, CS, 1, 1, 1.f, 0.f, 0);
            setgd(g.gd[4], H + H_W1TH, H + H_W1TL, MSZ, H + H_VH, H + H_VL, CHB,
                  F + F_DHID, 0, CHB, 0, 0, 0, 0, 0,
                  512, 256, 512, CS, 1, 1, 1.f, 0.f, 0);
            tgemm<<<dim3(2, 4, 40), 256, SMEM_TOTAL>>>(g);
        }

        k_ew12T<<<dim3(8, 16, 8), dim3(32, 8)>>>(lr1, cb);
        k_ekT<<<dim3(8, 16, 8), dim3(32, 8)>>>(kin, lr0, lr2, cb);

        // merged: out GEMM + dw GEMMs (dm = dw + dm*mi fused, sumsq partials)
        {
            TArgs g;
            setgd(g.gd[0], H + H_WCH + 8L * MSZ, H + H_WCL + 8L * MSZ, MSZ,
                  H + H_GTH, H + H_GTL, CHB,
                  out + (long)cb * DD, 0, TDSl, 0, 0, 0, 0, 0,
                  512, 256, 512, 1, DD, 1, 1.f, 0.f, 0);
            setgd(g.gd[1], H + H_DGH, H + H_DGL, CHB, H + H_K0H, H + H_K0L, CHB,
                  F + F_DM, F + F_DM, MSZ, 0, 0, 0, 0, 0,
                  512, 512, 256, 512, 1, 1 | 2 | 32, 1.f, 0.f, F + F_MI);
            setgd(g.gd[2], H + H_VTH, H + H_VTL, CHB, H + H_HLH, H + H_HLL, CHB,
                  F + F_DM + 8L * MSZ, F + F_DM + 8L * MSZ, MSZ, 0, 0, 0, 0, 0,
                  512, 512, 256, 512, 1, 1 | 2 | 32, 1.f, 0.f, F + F_MI);
            setgd(g.gd[3], H + H_DBH, H + H_DBL, CHB, H + H_K2H, H + H_K2L, CHB,
                  F + F_DM + 16L * MSZ, F + F_DM + 16L * MSZ, MSZ, 0, 0, 0, 0, 0,
                  512, 512, 256, 512, 1, 1 | 2 | 32, 1.f, 0.f, F + F_MI);
            tgemm<<<dim3(4, 4, 32), 256, SMEM_TOTAL>>>(g);
        }

        k_normfin<<<1, 24>>>();
        k_xsplit<<<dim3(16, 16, 24), dim3(32, 8)>>>();

        // Newton-Schulz (5 iters, 24 matrices); XT planes ping-pong per iter
        float* Xc = F + F_X0;
        float* Xn = F + F_X1;
        for (int it = 0; it < 5; it++) {
            float aa = NSC[it][0], bb = NSC[it][1], cc = NSC[it][2];
            long xtA_h = (it & 1) ? H_XT2H : H_XTH;
            long xtA_l = (it & 1) ? H_XT2L : H_XTL;
            long xtB_h = (it & 1) ? H_XTH : H_XT2H;
            long xtB_l = (it & 1) ? H_XTL : H_XT2L;
            // A = X @ X^T : symmetric triangle
            {
                TArgs g;
                for (int j = 0; j < 3; j++) {
                    long mb = (long)j * 8 * MSZ;
                    setgd(g.gd[j], H + H_XH + mb, H + H_XL + mb, MSZ,
                          H + H_XH + mb, H + H_XL + mb, MSZ,
                          F + F_AB + mb, 0, MSZ,
                          H + H_AH + mb, H + H_AL + mb, 0, 0, MSZ,
                          512, 512, 512, 512, 1, 1 | 4 | 16, 1.f, 0.f, 0);
                }
                tgemm<<<dim3(10, 1, 24), 256, SMEM_TOTAL>>>(g);
            }
            // B = b*A + c*(A@A) : symmetric triangle, bf16 planes only
            {
                TArgs g;
                for (int j = 0; j < 3; j++) {
                    long mb = (long)j * 8 * MSZ;
                    setgd(g.gd[j], H + H_AH + mb, H + H_AL + mb, MSZ,
                          H + H_AH + mb, H + H_AL + mb, MSZ,
                          0, F + F_AB + mb, MSZ,
                          H + H_BH + mb, H + H_BL + mb, 0, 0, MSZ,
                          512, 512, 512, 512, 1, 2 | 4 | 16, cc, bb, 0);
                }
                tgemm<<<dim3(10, 1, 24), 256, SMEM_TOTAL>>>(g);
            }
            // X' = a*X + B@X : reads XT[it&1], epilogue writes XT[(it+1)&1]
            {
                TArgs g;
                for (int j = 0; j < 3; j++) {
                    long mb = (long)j * 8 * MSZ;
                    setgd(g.gd[j], H + H_BH + mb, H + H_BL + mb, MSZ,
                          H + xtA_h + mb, H + xtA_l + mb, MSZ,
                          Xn + mb, Xc + mb, MSZ,
                          H + H_XH + mb, H + H_XL + mb,
                          H + xtB_h + mb, H + xtB_l + mb, MSZ,
                          512, 512, 512, 512, 1, 1 | 2 | 4 | 8, 1.f, aa, 0);
                }
                tgemm<<<dim3(4, 4, 24), 256, SMEM_TOTAL>>>(g);
            }
            float* tmp = Xc; Xc = Xn; Xn = tmp;
        }

        k_wupd<<<NMAT * 512, 128>>>(Xc);
        ts(F + F_WC + 8L * MSZ, MSZ, 512, 512, 0, 0, 0, H + H_W1TH, H + H_W1TL, MSZ, 8);
    }

    // final forward-only chunk
    {
        int cb = NCHUNK * CS;
        k_splitKQ<<<(int)(CHT / 256), 256>>>(kin, q, cb);
        {
            TArgs g;
            setgd(g.gd[0], H + H_WCH + 16L * MSZ, H + H_WCL + 16L * MSZ, MSZ,
                  H + H_QH, H + H_QL, CHB, F + F_HH, 0, CHB, 0, 0, 0, 0, 0,
                  512, 256, 512, CS, 1, 1, 1.f, 0.f, 0);
            setgd(g.gd[1], H + H_WCH, H + H_WCL, MSZ, H + H_QH, H + H_QL, CHB,
                  F + F_G0, 0, CHB, 0, 0, 0, 0, 0,
                  512, 256, 512, CS, 1, 1, 1.f, 0.f, 0);
            tgemm<<<dim3(2, 4, 16), 256, SMEM_TOTAL>>>(g);
        }
        k_ewfwdT<<<dim3(8, 16, 8), dim3(32, 8)>>>(cb);
        {
            TArgs g;
            setgd(g.gd[0], H + H_WCH + 8L * MSZ, H + H_WCL + 8L * MSZ, MSZ,
                  H + H_GTH, H + H_GTL, CHB,
                  out + (long)cb * DD, 0, TDSl, 0, 0, 0, 0, 0,
                  512, 256, 512, 1, DD, 1, 1.f, 0.f, 0);
            tgemm<<<dim3(2, 4, 8), 256, SMEM_TOTAL>>>(g);
        }
    }
}

// round 12
// speedup vs baseline: 2.7410x; 1.0396x over previous
#include <cuda_runtime.h>
#include <cuda_bf16.h>
#include <math.h>
#include <stdint.h>

// ---------------------------------------------------------------------------
// LaCT SWIGLU fast-weight attention — mma.sync bf16-split-3 GEMM engine v3.2.
// v3.1 + "planes are the truth" Newton-Schulz: all fp32 NS tensors removed.
// Flag 64 reads the beta/Dm term from bf16 hi+lo planes; X planes ping-pong
// (X/X2) like XT so epilogue writes never race mainloop/Dm reads; k_wupd
// reconstructs the final X from planes. Saves ~27% of NS memory traffic.
// ---------------------------------------------------------------------------

#define BH 8
#define TT 4096
#define DD 512
#define DI 512
#define CS 256
#define NCHUNK 15
#define NMAT 24
#define MSZ (512 * 512)
#define AST 40
#define PLANE_H (128 * AST)
#define STAGE_H (4 * PLANE_H)
#define NSTAGE 2
#define SMEM_TOTAL (NSTAGE * STAGE_H * 2)  // 81920 bytes

static constexpr long NM_  = (long)NMAT * MSZ;
static constexpr long W1M_ = 8L * MSZ;
static constexpr long CHB  = (long)CS * DD;
static constexpr long CHT  = (long)BH * CHB;
static constexpr long TDSl = (long)TT * DD;

// fp32 heap
static constexpr long F_WM = 0, F_WC = NM_, F_DM = 2 * NM_;
static constexpr long F_GBA = 3 * NM_, F_HBM = F_GBA + CHT, F_HH = F_HBM + CHT,
                      F_G0 = F_HH + CHT, F_DHID = F_G0 + CHT;
static constexpr long F_WNORM = F_DHID + CHT, F_MI = F_WNORM + NMAT * 512L,
                      F_MLI = F_MI + 8, F_RNS = F_MLI + 8,
                      F_RSP = F_RNS + NMAT, F_TOT = F_RSP + 512;
__device__ __align__(256) float g_f[F_TOT];

// bf16 heap
static constexpr long H_WCH = 0, H_WCL = NM_,
                      H_W1TH = 2 * NM_, H_W1TL = H_W1TH + W1M_,
                      H_XH = H_W1TL + W1M_, H_XL = H_XH + NM_,
                      H_X2H = H_XL + NM_, H_X2L = H_X2H + NM_,
                      H_XTH = H_X2L + NM_, H_XTL = H_XTH + NM_,
                      H_XT2H = H_XTL + NM_, H_XT2L = H_XT2H + NM_,
                      H_AH = H_XT2L + NM_, H_AL = H_AH + NM_,
                      H_BH = H_AL + NM_, H_BL = H_BH + NM_;
static constexpr long H_KH = H_BL + NM_, H_KL = H_KH + CHT, H_QH = H_KL + CHT,
                      H_QL = H_QH + CHT, H_VH = H_QL + CHT, H_VL = H_VH + CHT,
                      H_VTH = H_VL + CHT, H_VTL = H_VTH + CHT,
                      H_K0H = H_VTL + CHT, H_K0L = H_K0H + CHT,
                      H_K2H = H_K0L + CHT, H_K2L = H_K2H + CHT,
                      H_GTH = H_K2L + CHT, H_GTL = H_GTH + CHT,
                      H_HLH = H_GTL + CHT, H_HLL = H_HLH + CHT,
                      H_DGH = H_HLL + CHT, H_DGL = H_DGH + CHT,
                      H_DBH = H_DGL + CHT, H_DBL = H_DBH + CHT,
                      H_TOT = H_DBL + CHT;
__device__ __align__(256) __nv_bfloat16 g_h[H_TOT];

typedef __nv_bfloat16 bf;

// ------------------------- helpers -----------------------------------------
__device__ __forceinline__ uint32_t smem_u32(const void* p) {
    uint32_t a;
    asm("{ .reg .u64 t; cvta.to.shared.u64 t, %1; cvt.u32.u64 %0, t; }" : "=r"(a) : "l"(p));
    return a;
}
__device__ __forceinline__ void cp16(uint32_t dst, const void* src) {
    asm volatile("cp.async.cg.shared.global [%0], [%1], 16;" :: "r"(dst), "l"(src));
}
__device__ __forceinline__ void cp_commit() {
    asm volatile("cp.async.commit_group;" ::: "memory");
}
template <int N>
__device__ __forceinline__ void cp_wait() {
    asm volatile("cp.async.wait_group %0;" :: "n"(N) : "memory");
}
__device__ __forceinline__ void ldm4(uint32_t* f, uint32_t addr) {
    asm volatile("ldmatrix.sync.aligned.m8n8.x4.shared.b16 {%0,%1,%2,%3}, [%4];"
                 : "=r"(f[0]), "=r"(f[1]), "=r"(f[2]), "=r"(f[3]) : "r"(addr));
}
__device__ __forceinline__ void mma16816(float* c, const uint32_t* a, const uint32_t* b) {
    asm volatile("mma.sync.aligned.m16n8k16.row.col.f32.bf16.bf16.f32 "
                 "{%0,%1,%2,%3}, {%4,%5,%6,%7}, {%8,%9}, {%0,%1,%2,%3};"
                 : "+f"(c[0]), "+f"(c[1]), "+f"(c[2]), "+f"(c[3])
                 : "r"(a[0]), "r"(a[1]), "r"(a[2]), "r"(a[3]), "r"(b[0]), "r"(b[1]));
}
__device__ __forceinline__ void wsplit(bf* H, bf* L, long i, float v) {
    bf h = __float2bfloat16(v);
    H[i] = h;
    L[i] = __float2bfloat16(v - __bfloat162float(h));
}
__device__ __forceinline__ float sigf(float x) { return 1.f / (1.f + expf(-x)); }

// ------------------------- GEMM kernel --------------------------------------
// flags: 1=hasC, 2=Dm fp32, 4=hasO, 8=hasOT, 16=sym, 32=redsq, 64=Dm planes
struct GD {
    const bf *Ah, *Al, *Bh, *Bl;
    float* C;
    const float* Dm;
    const bf *DmH, *DmL;
    bf *OH, *OL, *OTH, *OTL;
    const float* betap;          // per-sub beta override (indexed by zb)
    long As, Bs, Cs, Os;
    int M, N, K, csr, csc, flags;
    float alpha, beta;
};
struct TArgs {
    GD gd[5];
};

__device__ __forceinline__ void ldplane(uint32_t smbase, const bf* g,
                                        int r0, int Kd, int kt, int tid) {
#pragma unroll
    for (int i = 0; i < 2; i++) {
        int idx = tid + i * 256;
        int row = idx >> 2;
        int ch = (idx & 3) << 3;
        const bf* src = g + (long)(r0 + row) * Kd + kt + ch;
        cp16(smbase + (uint32_t)(row * AST + ch) * 2u, src);
    }
}

__global__ __launch_bounds__(256, 2) void tgemm(const __grid_constant__ TArgs g) {
    extern __shared__ bf smh[];
    uint32_t smb = smem_u32(smh);

    const int tid = threadIdx.x;
    const int lane = tid & 31;
    const int wid = tid >> 5;
    const int wm = wid >> 2;
    const int wn = wid & 3;
    const int z = blockIdx.z;
    const GD& d = g.gd[z >> 3];
    const long zb = z & 7;
    const int flags = d.flags;

    int row0, col0, bi = 0, bj = 0;
    if (flags & 16) {
        int t = blockIdx.x;
        int i = 0;
        while (t >= (i + 1) * (i + 2) / 2) i++;
        bi = i; bj = t - i * (i + 1) / 2;
        row0 = bi * 128; col0 = bj * 128;
    } else {
        row0 = blockIdx.y * 128; col0 = blockIdx.x * 128;
        if (row0 >= d.M || col0 >= d.N) return;
    }

    const bf* Ah = d.Ah + zb * d.As;
    const bf* Al = d.Al + zb * d.As;
    const bf* Bh = d.Bh + zb * d.Bs;
    const bf* Bl = d.Bl + zb * d.Bs;
    const int Kd = d.K;
    const int nslab = Kd >> 5;

    float acc[4][4][4];
#pragma unroll
    for (int i = 0; i < 4; i++)
#pragma unroll
        for (int j = 0; j < 4; j++)
#pragma unroll
            for (int r = 0; r < 4; r++) acc[i][j][r] = 0.f;

    const int lrow = lane & 15;
    const int lcol = (lane >> 4) << 3;

    // prologue: stage 0
    {
        ldplane(smb,                   Ah, row0, Kd, 0, tid);
        ldplane(smb + PLANE_H * 2,     Al, row0, Kd, 0, tid);
        ldplane(smb + 2 * PLANE_H * 2, Bh, col0, Kd, 0, tid);
        ldplane(smb + 3 * PLANE_H * 2, Bl, col0, Kd, 0, tid);
        cp_commit();
    }

    for (int s = 0; s < nslab; s++) {
        if (s + 1 < nslab) {
            uint32_t sb = smb + (uint32_t)(((s + 1) & 1) * STAGE_H) * 2u;
            int kt = (s + 1) << 5;
            ldplane(sb,                   Ah, row0, Kd, kt, tid);
            ldplane(sb + PLANE_H * 2,     Al, row0, Kd, kt, tid);
            ldplane(sb + 2 * PLANE_H * 2, Bh, col0, Kd, kt, tid);
            ldplane(sb + 3 * PLANE_H * 2, Bl, col0, Kd, kt, tid);
            cp_commit();
            cp_wait<1>();
        } else {
            cp_wait<0>();
        }
        __syncthreads();

        uint32_t sb = smb + (uint32_t)((s & 1) * STAGE_H) * 2u;
#pragma unroll
        for (int k16 = 0; k16 < 2; k16++) {
            const int kh = k16 * 16 + lcol;
            uint32_t bhf[2][4], blf[2][4];
#pragma unroll
            for (int pr = 0; pr < 2; pr++) {
                int br = wn * 32 + pr * 16 + lrow;
                uint32_t off = (uint32_t)(br * AST + kh) * 2u;
                ldm4(bhf[pr], sb + 2 * PLANE_H * 2 + off);
                ldm4(blf[pr], sb + 3 * PLANE_H * 2 + off);
            }
#pragma unroll
            for (int mt = 0; mt < 4; mt++) {
                uint32_t ahf[4], alf[4];
                int ar = wm * 64 + mt * 16 + lrow;
                uint32_t off = (uint32_t)(ar * AST + kh) * 2u;
                ldm4(ahf, sb + off);
                ldm4(alf, sb + PLANE_H * 2 + off);
#pragma unroll
                for (int nt = 0; nt < 4; nt++) {
                    int pr = nt >> 1, hi = nt & 1;
                    uint32_t bh2[2] = {bhf[pr][hi], bhf[pr][hi + 2]};
                    uint32_t bl2[2] = {blf[pr][hi], blf[pr][hi + 2]};
                    mma16816(acc[mt][nt], ahf, bh2);
                    mma16816(acc[mt][nt], ahf, bl2);
                    mma16816(acc[mt][nt], alf, bh2);
                }
            }
        }
        __syncthreads();
    }

    // epilogue
    float* tsb = (float*)smh;
    float* C = d.C + zb * d.Cs;
    const float* Dm = d.Dm + zb * d.Cs;
    const bf* DmH = d.DmH + zb * d.Cs;
    const bf* DmL = d.DmL + zb * d.Cs;
    bf* oh = d.OH + zb * d.Os;
    bf* ol = d.OL + zb * d.Os;
    const float bcoef = d.betap ? d.betap[zb] : d.beta;
    const int gr = lane >> 2, gc = (lane & 3) * 2;
    const int domirror = (flags & 16) && (bi != bj);
    float ssq = 0.f;
#pragma unroll
    for (int mt = 0; mt < 4; mt++) {
#pragma unroll
        for (int nt = 0; nt < 4; nt++) {
#pragma unroll
            for (int rg = 0; rg < 4; rg++) {
                int rl = wm * 64 + mt * 16 + gr + ((rg >> 1) << 3);
                int cl = wn * 32 + nt * 8 + gc + (rg & 1);
                int r = row0 + rl, c = col0 + cl;
                long off = (long)r * d.csr + (long)c * d.csc;
                float val = d.alpha * acc[mt][nt][rg];
                if (flags & 2) val += bcoef * Dm[off];
                if (flags & 64)
                    val += bcoef * (__bfloat162float(DmH[off]) + __bfloat162float(DmL[off]));
                if (flags & 1) C[off] = val;
                if (flags & 32) ssq += val * val;
                bf vh = __float2bfloat16(val);
                bf vl = __float2bfloat16(val - __bfloat162float(vh));
                if (flags & 4) { oh[off] = vh; ol[off] = vl; }
                if (domirror) {
                    long offm = (long)c * d.csr + (long)r * d.csc;
                    if (flags & 1) C[offm] = val;
                    if (flags & 4) { oh[offm] = vh; ol[offm] = vl; }
                }
                if (flags & 8) tsb[rl * 129 + cl] = val;
            }
        }
    }
    if (flags & 32) {
#pragma unroll
        for (int o = 16; o > 0; o >>= 1) ssq += __shfl_xor_sync(0xffffffffu, ssq, o);
        float* rs = (float*)smh;
        if (lane == 0) rs[wid] = ssq;
        __syncthreads();
        if (tid == 0) {
            float tot = 0.f;
#pragma unroll
            for (int w = 0; w < 8; w++) tot += rs[w];
            g_f[F_RSP + (long)z * 16 + blockIdx.y * 4 + blockIdx.x] = tot;
        }
    }
    if (flags & 8) {
        __syncthreads();
        bf* oth = d.OTH + zb * d.Os;
        bf* otl = d.OTL + zb * d.Os;
#pragma unroll 4
        for (int i = 0; i < 64; i++) {
            int idx = tid + i * 256;
            int cl = idx >> 7;
            int rl = idx & 127;
            float v = tsb[rl * 129 + cl];
            long off = (long)(col0 + cl) * 512 + row0 + rl;
            bf h = __float2bfloat16(v);
            oth[off] = h;
            otl[off] = __float2bfloat16(v - __bfloat162float(h));
        }
    }
}

// ------------------------- transpose/split (fp32 src -> planes) -------------
struct TSArgs {
    const float* src; long sbs; int srows, scols;
    bf *pH, *pL; long pbs;
    bf *tH, *tL; long tbs;
};
__global__ void k_tsplit(const __grid_constant__ TSArgs a) {
    __shared__ float tile[32][33];
    int z = blockIdx.z;
    const float* S = a.src + (long)z * a.sbs;
    int c0 = blockIdx.x * 32, r0 = blockIdx.y * 32;
    int tx = threadIdx.x, ty = threadIdx.y;
#pragma unroll
    for (int j = 0; j < 4; j++) {
        int r = r0 + ty + j * 8;
        float v = S[(long)r * a.scols + c0 + tx];
        tile[ty + j * 8][tx] = v;
        if (a.pH) {
            long o = (long)z * a.pbs + (long)r * a.scols + c0 + tx;
            wsplit(a.pH, a.pL, o, v);
        }
    }
    __syncthreads();
    if (a.tH) {
#pragma unroll
        for (int j = 0; j < 4; j++) {
            int c = c0 + ty + j * 8;
            float v = tile[tx][ty + j * 8];
            long o = (long)z * a.tbs + (long)c * a.srows + r0 + tx;
            wsplit(a.tH, a.tL, o, v);
        }
    }
}

// ------------------------- elementwise/fused kernels ------------------------
__global__ void k_init(const float* w0, const float* w1, const float* w2) {
    int row = blockIdx.x;
    int m = row >> 9, w = m >> 3, bh = m & 7, r = row & 511;
    const float* src = (w == 0 ? w0 : (w == 1 ? w1 : w2)) + (long)bh * MSZ + (long)r * 512;
    long mo = (long)m * MSZ + (long)r * 512;
    int t = threadIdx.x;
    float ss = 0.f;
#pragma unroll
    for (int j = 0; j < 4; j++) {
        int c = t + j * 128;
        float v = src[c];
        g_f[F_WM + mo + c] = v;
        g_f[F_WC + mo + c] = v;
        g_f[F_DM + mo + c] = 0.f;
        wsplit(g_h + H_WCH, g_h + H_WCL, mo + c, v);
        ss += v * v;
    }
    __shared__ float red[128];
    red[t] = ss; __syncthreads();
    for (int s = 64; s > 0; s >>= 1) { if (t < s) red[t] += red[t + s]; __syncthreads(); }
    if (t == 0) g_f[F_WNORM + (long)m * 512 + r] = sqrtf(red[0]);
}

__global__ void k_splitKQ(const float* kin, const float* q, int cbase) {
    long idx = blockIdx.x * 256L + threadIdx.x;
    int dd = idx & 511;
    int t = (int)((idx >> 9) & 255);
    int bh = (int)(idx >> 17);
    long so = (long)bh * TDSl + (long)(cbase + t) * DD + dd;
    wsplit(g_h + H_KH, g_h + H_KL, idx, kin[so]);
    wsplit(g_h + H_QH, g_h + H_QL, idx, q[so]);
}

// ew1 quantities + gate-hidden transpose (GT planes), tiled over (di, t)
__global__ void k_ew12T(const float* lr1, int cbase) {
    __shared__ float tile[32][33];
    int bh = blockIdx.z;
    int t0 = blockIdx.x * 32, di0 = blockIdx.y * 32;
    int tx = threadIdx.x, ty = threadIdx.y;
    float l1 = lr1[(long)bh * TT + cbase + t0 + tx];
#pragma unroll
    for (int j = 0; j < 4; j++) {
        long idx = (long)bh * CHB + (long)(di0 + ty + 8 * j) * CS + t0 + tx;
        float gba = g_f[F_GBA + idx], hbm = g_f[F_HBM + idx], dh = g_f[F_DHID + idx];
        float sg = sigf(gba), sil = gba * sg;
        wsplit(g_h + H_HLH, g_h + H_HLL, idx, sil * hbm * l1);
        wsplit(g_h + H_DBH, g_h + H_DBL, idx, dh * sil);
        float dgate = dh * hbm;
        wsplit(g_h + H_DGH, g_h + H_DGL, idx, dgate * sg * (1.f + gba * (1.f - sg)));
        float g0v = g_f[F_G0 + idx], hv = g_f[F_HH + idx];
        tile[ty + 8 * j][tx] = g0v * sigf(g0v) * hv;
    }
    __syncthreads();
#pragma unroll
    for (int j = 0; j < 4; j++) {
        long o = (long)bh * CHB + (long)(t0 + ty + 8 * j) * DI + di0 + tx;
        wsplit(g_h + H_GTH, g_h + H_GTL, o, tile[tx][ty + 8 * j]);
    }
}

// forward-only gate-hidden transpose (final chunk)
__global__ void k_ewfwdT(int cbase) {
    __shared__ float tile[32][33];
    int bh = blockIdx.z;
    int t0 = blockIdx.x * 32, di0 = blockIdx.y * 32;
    int tx = threadIdx.x, ty = threadIdx.y;
#pragma unroll
    for (int j = 0; j < 4; j++) {
        long idx = (long)bh * CHB + (long)(di0 + ty + 8 * j) * CS + t0 + tx;
        float g0v = g_f[F_G0 + idx], hv = g_f[F_HH + idx];
        tile[ty + 8 * j][tx] = g0v * sigf(g0v) * hv;
    }
    __syncthreads();
#pragma unroll
    for (int j = 0; j < 4; j++) {
        long o = (long)bh * CHB + (long)(t0 + ty + 8 * j) * DI + di0 + tx;
        wsplit(g_h + H_GTH, g_h + H_GTL, o, tile[tx][ty + 8 * j]);
    }
}

// k*lr -> transposed K0/K2 planes, tiled over (t, d)
__global__ void k_ekT(const float* kin, const float* lr0, const float* lr2, int cbase) {
    __shared__ float tile[32][33];
    int bh = blockIdx.z;
    int t0 = blockIdx.x * 32, d0 = blockIdx.y * 32;
    int tx = threadIdx.x, ty = threadIdx.y;
#pragma unroll
    for (int j = 0; j < 4; j++)
        tile[ty + 8 * j][tx] =
            kin[(long)bh * TDSl + (long)(cbase + t0 + ty + 8 * j) * DD + d0 + tx];
    __syncthreads();
    float l0 = lr0[(long)bh * TT + cbase + t0 + tx];
    float l2 = lr2[(long)bh * TT + cbase + t0 + tx];
#pragma unroll
    for (int j = 0; j < 4; j++) {
        long o = (long)bh * CHB + (long)(d0 + ty + 8 * j) * CS + t0 + tx;
        float kv = tile[tx][ty + 8 * j];
        wsplit(g_h + H_K0H, g_h + H_K0L, o, kv * l0);
        wsplit(g_h + H_K2H, g_h + H_K2L, o, kv * l2);
    }
}

__global__ void k_scalars(const float* mom, const float* mlt, int cbase) {
    int bh = blockIdx.x;
    int t = threadIdx.x;
    __shared__ float r1[256], r2[256];
    r1[t] = mom[(long)bh * TT + cbase + t];
    r2[t] = mlt[(long)bh * TT + cbase + t];
    __syncthreads();
    for (int s = 128; s > 0; s >>= 1) {
        if (t < s) { r1[t] += r1[t + s]; r2[t] += r2[t + s]; }
        __syncthreads();
    }
    if (t == 0) { g_f[F_MI + bh] = r1[0] * (1.f / CS); g_f[F_MLI + bh] = r2[0] * (1.f / CS); }
}

__global__ void k_normfin() {
    int m = threadIdx.x;  // 24
    float s = 0.f;
#pragma unroll
    for (int i = 0; i < 16; i++) s += g_f[F_RSP + (long)(m + 8) * 16 + i];
    g_f[F_RNS + m] = 1.f / (sqrtf(s) + 1e-7f);
}

// dm*rns -> X planes (pair 0) + XT planes (pair 0), tiled
__global__ void k_xsplit() {
    __shared__ float tile[32][33];
    int m = blockIdx.z;
    int c0 = blockIdx.x * 32, r0 = blockIdx.y * 32;
    int tx = threadIdx.x, ty = threadIdx.y;
    float rn = g_f[F_RNS + m];
#pragma unroll
    for (int j = 0; j < 4; j++) {
        long i = (long)m * MSZ + (long)(r0 + ty + 8 * j) * 512 + c0 + tx;
        float v = g_f[F_DM + i] * rn;
        wsplit(g_h + H_XH, g_h + H_XL, i, v);
        tile[ty + 8 * j][tx] = v;
    }
    __syncthreads();
#pragma unroll
    for (int j = 0; j < 4; j++) {
        long o = (long)m * MSZ + (long)(c0 + ty + 8 * j) * 512 + r0 + tx;
        wsplit(g_h + H_XTH, g_h + H_XTL, o, tile[tx][ty + 8 * j]);
    }
}

// weight update: X read from bf16 hi+lo planes
__global__ void k_wupd(const bf* xh, const bf* xl) {
    int row = blockIdx.x;
    int m = row >> 9, bh = m & 7, r = row & 511;
    long mo = (long)m * MSZ + (long)r * 512;
    float ml = g_f[F_MLI + bh];
    int t = threadIdx.x;
    float vals[4];
    float ss = 0.f;
#pragma unroll
    for (int j = 0; j < 4; j++) {
        int c = t + j * 128;
        float xv = __bfloat162float(xh[mo + c]) + __bfloat162float(xl[mo + c]);
        float v = g_f[F_WM + mo + c] + xv * ml;
        g_f[F_WM + mo + c] = v;
        vals[j] = v;
        ss += v * v;
    }
    __shared__ float red[128];
    red[t] = ss; __syncthreads();
    for (int s = 64; s > 0; s >>= 1) { if (t < s) red[t] += red[t + s]; __syncthreads(); }
    float scale = g_f[F_WNORM + (long)m * 512 + r] / (sqrtf(red[0]) + 1e-5f);
#pragma unroll
    for (int j = 0; j < 4; j++) {
        int c = t + j * 128;
        float w = vals[j] * scale;
        g_f[F_WC + mo + c] = w;
        wsplit(g_h + H_WCH, g_h + H_WCL, mo + c, w);
    }
}

// ------------------------- host orchestration -------------------------------
static void setgd(GD& d, const bf* Ah, const bf* Al, long As,
                  const bf* Bh, const bf* Bl, long Bs,
                  float* C, const float* Dm, const bf* DmH, const bf* DmL, long Cs,
                  bf* OH, bf* OL, bf* OTH, bf* OTL, long Os,
                  int M, int N, int K, int csr, int csc, int flags,
                  float alpha, float beta, const float* betap) {
    d.Ah = Ah; d.Al = Al; d.Bh = Bh; d.Bl = Bl;
    d.C = C; d.Dm = Dm; d.DmH = DmH; d.DmL = DmL;
    d.OH = OH; d.OL = OL; d.OTH = OTH; d.OTL = OTL;
    d.betap = betap;
    d.As = As; d.Bs = Bs; d.Cs = Cs; d.Os = Os;
    d.M = M; d.N = N; d.K = K; d.csr = csr; d.csc = csc; d.flags = flags;
    d.alpha = alpha; d.beta = beta;
}

static void ts(const float* src, long sbs, int srows, int scols,
               bf* pH, bf* pL, long pbs, bf* tH, bf* tL, long tbs, int batch) {
    TSArgs a;
    a.src = src; a.sbs = sbs; a.srows = srows; a.scols = scols;
    a.pH = pH; a.pL = pL; a.pbs = pbs;
    a.tH = tH; a.tL = tL; a.tbs = tbs;
    k_tsplit<<<dim3(scols / 32, srows / 32, batch), dim3(32, 8)>>>(a);
}

static const float NSC[5][3] = {
    {4.0848f, -6.8946f, 2.927f},
    {3.9505f, -6.3029f, 2.6377f},
    {3.7418f, -5.5913f, 2.3037f},
    {2.8769f, -3.1427f, 1.2046f},
    {2.8366f, -3.0525f, 1.2012f}};

extern "C" void kernel_launch(void* const* d_in, const int* in_sizes, int n_in,
                              void* d_out, int out_size) {
    const float* w0  = (const float*)d_in[0];
    const float* w1  = (const float*)d_in[1];
    const float* w2  = (const float*)d_in[2];
    const float* q   = (const float*)d_in[3];
    const float* kin = (const float*)d_in[4];
    const float* v   = (const float*)d_in[5];
    const float* lr0 = (const float*)d_in[6];
    const float* lr1 = (const float*)d_in[7];
    const float* lr2 = (const float*)d_in[8];
    const float* mom = (const float*)d_in[9];
    const float* mlt = (const float*)d_in[10];
    float* out = (float*)d_out;

    static int smset = 0;
    if (!smset) {
        cudaFuncSetAttribute(tgemm, cudaFuncAttributeMaxDynamicSharedMemorySize, SMEM_TOTAL);
        smset = 1;
    }

    float* F;
    bf* H;
    cudaGetSymbolAddress((void**)&F, g_f);
    cudaGetSymbolAddress((void**)&H, g_h);

    k_init<<<NMAT * 512, 128>>>(w0, w1, w2);
    ts(F + F_WC + 8L * MSZ, MSZ, 512, 512, 0, 0, 0, H + H_W1TH, H + H_W1TL, MSZ, 8);

    for (int ci = 0; ci < NCHUNK; ci++) {
        int cb = ci * CS;

        k_scalars<<<BH, 256>>>(mom, mlt, cb);
        k_splitKQ<<<(int)(CHT / 256), 256>>>(kin, q, cb);
        ts(v + (long)cb * DD, TDSl, 256, 512,
           H + H_VH, H + H_VL, CHB, H + H_VTH, H + H_VTL, CHB, 8);

        // activation GEMMs: 5 groups of 8 -> one launch
        {
            TArgs g;
            setgd(g.gd[0], H + H_WCH, H + H_WCL, MSZ, H + H_KH, H + H_KL, CHB,
                  F + F_GBA, 0, 0, 0, CHB, 0, 0, 0, 0, 0,
                  512, 256, 512, CS, 1, 1, 1.f, 0.f, 0);
            setgd(g.gd[1], H + H_WCH + 16L * MSZ, H + H_WCL + 16L * MSZ, MSZ,
                  H + H_KH, H + H_KL, CHB, F + F_HBM, 0, 0, 0, CHB, 0, 0, 0, 0, 0,
                  512, 256, 512, CS, 1, 1, 1.f, 0.f, 0);
            setgd(g.gd[2], H + H_WCH + 16L * MSZ, H + H_WCL + 16L * MSZ, MSZ,
                  H + H_QH, H + H_QL, CHB, F + F_HH, 0, 0, 0, CHB, 0, 0, 0, 0, 0,
                  512, 256, 512, CS, 1, 1, 1.f, 0.f, 0);
            setgd(g.gd[3], H + H_WCH, H + H_WCL, MSZ, H + H_QH, H + H_QL, CHB,
                  F + F_G0, 0, 0, 0, CHB, 0, 0, 0, 0, 0,
                  512, 256, 512, CS, 1, 1, 1.f, 0.f, 0);
            setgd(g.gd[4], H + H_W1TH, H + H_W1TL, MSZ, H + H_VH, H + H_VL, CHB,
                  F + F_DHID, 0, 0, 0, CHB, 0, 0, 0, 0, 0,
                  512, 256, 512, CS, 1, 1, 1.f, 0.f, 0);
            tgemm<<<dim3(2, 4, 40), 256, SMEM_TOTAL>>>(g);
        }

        k_ew12T<<<dim3(8, 16, 8), dim3(32, 8)>>>(lr1, cb);
        k_ekT<<<dim3(8, 16, 8), dim3(32, 8)>>>(kin, lr0, lr2, cb);

        // merged: out GEMM + dw GEMMs (dm = dw + dm*mi fused, sumsq partials)
        {
            TArgs g;
            setgd(g.gd[0], H + H_WCH + 8L * MSZ, H + H_WCL + 8L * MSZ, MSZ,
                  H + H_GTH, H + H_GTL, CHB,
                  out + (long)cb * DD, 0, 0, 0, TDSl, 0, 0, 0, 0, 0,
                  512, 256, 512, 1, DD, 1, 1.f, 0.f, 0);
            setgd(g.gd[1], H + H_DGH, H + H_DGL, CHB, H + H_K0H, H + H_K0L, CHB,
                  F + F_DM, F + F_DM, 0, 0, MSZ, 0, 0, 0, 0, 0,
                  512, 512, 256, 512, 1, 1 | 2 | 32, 1.f, 0.f, F + F_MI);
            setgd(g.gd[2], H + H_VTH, H + H_VTL, CHB, H + H_HLH, H + H_HLL, CHB,
                  F + F_DM + 8L * MSZ, F + F_DM + 8L * MSZ, 0, 0, MSZ, 0, 0, 0, 0, 0,
                  512, 512, 256, 512, 1, 1 | 2 | 32, 1.f, 0.f, F + F_MI);
            setgd(g.gd[3], H + H_DBH, H + H_DBL, CHB, H + H_K2H, H + H_K2L, CHB,
                  F + F_DM + 16L * MSZ, F + F_DM + 16L * MSZ, 0, 0, MSZ, 0, 0, 0, 0, 0,
                  512, 512, 256, 512, 1, 1 | 2 | 32, 1.f, 0.f, F + F_MI);
            tgemm<<<dim3(4, 4, 32), 256, SMEM_TOTAL>>>(g);
        }

        k_normfin<<<1, 24>>>();
        k_xsplit<<<dim3(16, 16, 24), dim3(32, 8)>>>();

        // Newton-Schulz (5 iters, 24 matrices); X and XT planes ping-pong
        for (int it = 0; it < 5; it++) {
            float aa = NSC[it][0], bb = NSC[it][1], cc = NSC[it][2];
            long xA_h  = (it & 1) ? H_X2H : H_XH;      // read X pair
            long xA_l  = (it & 1) ? H_X2L : H_XL;
            long xB_h  = (it & 1) ? H_XH : H_X2H;      // write X pair
            long xB_l  = (it & 1) ? H_XL : H_X2L;
            long xtA_h = (it & 1) ? H_XT2H : H_XTH;    // read XT pair
            long xtA_l = (it & 1) ? H_XT2L : H_XTL;
            long xtB_h = (it & 1) ? H_XTH : H_XT2H;    // write XT pair
            long xtB_l = (it & 1) ? H_XTL : H_XT2L;
            // A = X @ X^T : symmetric triangle, planes only
            {
                TArgs g;
                for (int j = 0; j < 3; j++) {
                    long mb = (long)j * 8 * MSZ;
                    setgd(g.gd[j], H + xA_h + mb, H + xA_l + mb, MSZ,
                          H + xA_h + mb, H + xA_l + mb, MSZ,
                          0, 0, 0, 0, MSZ,
                          H + H_AH + mb, H + H_AL + mb, 0, 0, MSZ,
                          512, 512, 512, 512, 1, 4 | 16, 1.f, 0.f, 0);
                }
                tgemm<<<dim3(10, 1, 24), 256, SMEM_TOTAL>>>(g);
            }
            // B = b*A + c*(A@A) : symmetric triangle, beta term from A planes
            {
                TArgs g;
                for (int j = 0; j < 3; j++) {
                    long mb = (long)j * 8 * MSZ;
                    setgd(g.gd[j], H + H_AH + mb, H + H_AL + mb, MSZ,
                          H + H_AH + mb, H + H_AL + mb, MSZ,
                          0, 0, H + H_AH + mb, H + H_AL + mb, MSZ,
                          H + H_BH + mb, H + H_BL + mb, 0, 0, MSZ,
                          512, 512, 512, 512, 1, 4 | 16 | 64, cc, bb, 0);
                }
                tgemm<<<dim3(10, 1, 24), 256, SMEM_TOTAL>>>(g);
            }
            // X' = a*X + B@X : Dm from X[p] planes; writes X[1-p] + XT[1-p]
            {
                TArgs g;
                for (int j = 0; j < 3; j++) {
                    long mb = (long)j * 8 * MSZ;
                    setgd(g.gd[j], H + H_BH + mb, H + H_BL + mb, MSZ,
                          H + xtA_h + mb, H + xtA_l + mb, MSZ,
                          0, 0, H + xA_h + mb, H + xA_l + mb, MSZ,
                          H + xB_h + mb, H + xB_l + mb,
                          H + xtB_h + mb, H + xtB_l + mb, MSZ,
                          512, 512, 512, 512, 1, 4 | 8 | 64, 1.f, aa, 0);
                }
                tgemm<<<dim3(4, 4, 24), 256, SMEM_TOTAL>>>(g);
            }
        }

        // after 5 iters the final X lives in pair 1 (X2 planes)
        k_wupd<<<NMAT * 512, 128>>>(H + H_X2H, H + H_X2L);
        ts(F + F_WC + 8L * MSZ, MSZ, 512, 512, 0, 0, 0, H + H_W1TH, H + H_W1TL, MSZ, 8);
    }

    // final forward-only chunk
    {
        int cb = NCHUNK * CS;
        k_splitKQ<<<(int)(CHT / 256), 256>>>(kin, q, cb);
        {
            TArgs g;
            setgd(g.gd[0], H + H_WCH + 16L * MSZ, H + H_WCL + 16L * MSZ, MSZ,
                  H + H_QH, H + H_QL, CHB, F + F_HH, 0, 0, 0, CHB, 0, 0, 0, 0, 0,
                  512, 256, 512, CS, 1, 1, 1.f, 0.f, 0);
            setgd(g.gd[1], H + H_WCH, H + H_WCL, MSZ, H + H_QH, H + H_QL, CHB,
                  F + F_G0, 0, 0, 0, CHB, 0, 0, 0, 0, 0,
                  512, 256, 512, CS, 1, 1, 1.f, 0.f, 0);
            tgemm<<<dim3(2, 4, 16), 256, SMEM_TOTAL>>>(g);
        }
        k_ewfwdT<<<dim3(8, 16, 8), dim3(32, 8)>>>(cb);
        {
            TArgs g;
            setgd(g.gd[0], H + H_WCH + 8L * MSZ, H + H_WCL + 8L * MSZ, MSZ,
                  H + H_GTH, H + H_GTL, CHB,
                  out + (long)cb * DD, 0, 0, 0, TDSl, 0, 0, 0, 0, 0,
                  512, 256, 512, 1, DD, 1, 1.f, 0.f, 0);
            tgemm<<<dim3(2, 4, 8), 256, SMEM_TOTAL>>>(g);
        }
    }
}